// round 10
// baseline (speedup 1.0000x reference)

#include <cuda_runtime.h>
#include <math.h>
#include <stdint.h>

#define B_  2
#define S_  2048
#define H_  16
#define D_  64
#define DM_ 1024
#define BH_ (B_ * H_)

// -------- scratch (device globals: allocation-free) --------
__device__ float g_q[(size_t)BH_ * S_ * D_];
__device__ float g_k[(size_t)BH_ * S_ * D_];
__device__ float g_v[(size_t)BH_ * S_ * D_];
__device__ float g_o2[(size_t)BH_ * S_ * D_];
__device__ float g_ctx[(size_t)BH_ * S_ * D_];
__device__ float g_normed[(size_t)B_ * S_ * DM_];

// ============================================================
// Kernel 1: QKV projection.  C[m,n] = sum_k x[m,k]*W[n,k] + b[n]
// M = B*S = 4096, N = 3*DM = 3072, K = 1024.
// Epilogue scatters into g_q/g_k/g_v in (b,h,s,d) layout.
// ============================================================
__global__ void __launch_bounds__(256) qkv_gemm_kernel(
    const float* __restrict__ x, const float* __restrict__ W,
    const float* __restrict__ bias) {
    __shared__ float As[16][68];
    __shared__ float Bs[16][68];
    const int bm = blockIdx.y * 64;
    const int bn = blockIdx.x * 64;
    const int tid = threadIdx.x;
    const int tx = tid & 15, ty = tid >> 4;
    const int lr = tid >> 2;             // 0..63 tile row
    const int lc = (tid & 3) * 4;        // 0,4,8,12 within BK=16

    float acc[4][4] = {};
    for (int k0 = 0; k0 < 1024; k0 += 16) {
        float4 a = *(const float4*)&x[(size_t)(bm + lr) * 1024 + k0 + lc];
        float4 b = *(const float4*)&W[(size_t)(bn + lr) * 1024 + k0 + lc];
        As[lc + 0][lr] = a.x; As[lc + 1][lr] = a.y;
        As[lc + 2][lr] = a.z; As[lc + 3][lr] = a.w;
        Bs[lc + 0][lr] = b.x; Bs[lc + 1][lr] = b.y;
        Bs[lc + 2][lr] = b.z; Bs[lc + 3][lr] = b.w;
        __syncthreads();
#pragma unroll
        for (int kk = 0; kk < 16; kk++) {
            float av[4], bv[4];
#pragma unroll
            for (int i = 0; i < 4; i++) av[i] = As[kk][ty * 4 + i];
#pragma unroll
            for (int j = 0; j < 4; j++) bv[j] = Bs[kk][tx * 4 + j];
#pragma unroll
            for (int i = 0; i < 4; i++)
#pragma unroll
                for (int j = 0; j < 4; j++) acc[i][j] += av[i] * bv[j];
        }
        __syncthreads();
    }
    // scatter epilogue
#pragma unroll
    for (int i = 0; i < 4; i++) {
        const int m = bm + ty * 4 + i;
        const int b_idx = m / S_, s_idx = m % S_;
#pragma unroll
        for (int j = 0; j < 4; j++) {
            const int n = bn + tx * 4 + j;
            const float val = acc[i][j] + bias[n];
            const int which = n >> 10;       // /DM
            const int wi = n & 1023;
            const int h = wi >> 6, d = wi & 63;
            float* dst = (which == 0) ? g_q : (which == 1) ? g_k : g_v;
            dst[(((size_t)b_idx * H_ + h) * S_ + s_idx) * D_ + d] = val;
        }
    }
}

// ============================================================
// Kernel 2/3: causal no-softmax attention pass (flash-style).
// MODE 0: Qeff = q,        V = k,  Out = o2
// MODE 1: Qeff = 2q - o2,  V = v,  Out = ctx
// Block: 64 queries x D=64, loops over key blocks j <= qi.
// ============================================================
template <int MODE>
__global__ void __launch_bounds__(256) attn_kernel() {
    extern __shared__ float sm[];
    float* Qs = sm;                       // 64 x 65
    float* Ks = sm + 64 * 65;
    float* Ss = sm + 2 * 64 * 65;
    float* Vs = (MODE == 0) ? Ks : sm + 3 * 64 * 65;

    const int bh = blockIdx.y;
    const int qi = blockIdx.x;
    const size_t base = (size_t)bh * S_ * D_;
    const int t0 = qi * 64;
    const int tid = threadIdx.x;
    const int tx = tid & 15, ty = tid >> 4;
    const int lr = tid >> 2;              // row loader 0..63
    const int lc0 = (tid & 3) * 16;       // 16 floats per thread

    // load Q block (Qeff)
    {
        const float* qp = g_q + base + (size_t)(t0 + lr) * D_;
        const float* op = g_o2 + base + (size_t)(t0 + lr) * D_;
#pragma unroll
        for (int u = 0; u < 4; u++) {
            const int c = lc0 + u * 4;
            float4 a = *(const float4*)(qp + c);
            if (MODE == 1) {
                float4 o = *(const float4*)(op + c);
                a.x = 2.f * a.x - o.x; a.y = 2.f * a.y - o.y;
                a.z = 2.f * a.z - o.z; a.w = 2.f * a.w - o.w;
            }
            Qs[lr * 65 + c + 0] = a.x; Qs[lr * 65 + c + 1] = a.y;
            Qs[lr * 65 + c + 2] = a.z; Qs[lr * 65 + c + 3] = a.w;
        }
    }

    float acc[4][4] = {};
    for (int j = 0; j <= qi; j++) {
        const int s0 = j * 64;
        __syncthreads();   // prev iter done with Ks/Vs/Ss
        {
            const float* kp = g_k + base + (size_t)(s0 + lr) * D_;
#pragma unroll
            for (int u = 0; u < 4; u++) {
                const int c = lc0 + u * 4;
                float4 a = *(const float4*)(kp + c);
                Ks[lr * 65 + c + 0] = a.x; Ks[lr * 65 + c + 1] = a.y;
                Ks[lr * 65 + c + 2] = a.z; Ks[lr * 65 + c + 3] = a.w;
            }
            if (MODE == 1) {
                const float* vp = g_v + base + (size_t)(s0 + lr) * D_;
#pragma unroll
                for (int u = 0; u < 4; u++) {
                    const int c = lc0 + u * 4;
                    float4 a = *(const float4*)(vp + c);
                    Vs[lr * 65 + c + 0] = a.x; Vs[lr * 65 + c + 1] = a.y;
                    Vs[lr * 65 + c + 2] = a.z; Vs[lr * 65 + c + 3] = a.w;
                }
            }
        }
        __syncthreads();

        // phase 1: S = Qeff * K^T  (mask s>t; only bites on diagonal block)
        float sc[4][4] = {};
#pragma unroll 16
        for (int d = 0; d < 64; d++) {
            float av[4], bv[4];
#pragma unroll
            for (int i = 0; i < 4; i++) av[i] = Qs[(ty * 4 + i) * 65 + d];
#pragma unroll
            for (int jj = 0; jj < 4; jj++) bv[jj] = Ks[(tx * 4 + jj) * 65 + d];
#pragma unroll
            for (int i = 0; i < 4; i++)
#pragma unroll
                for (int jj = 0; jj < 4; jj++) sc[i][jj] += av[i] * bv[jj];
        }
#pragma unroll
        for (int i = 0; i < 4; i++) {
            const int tt = t0 + ty * 4 + i;
#pragma unroll
            for (int jj = 0; jj < 4; jj++) {
                const int ss = s0 + tx * 4 + jj;
                Ss[(ty * 4 + i) * 65 + tx * 4 + jj] = (ss <= tt) ? sc[i][jj] : 0.f;
            }
        }
        __syncthreads();

        // phase 2: O += S * V
#pragma unroll 16
        for (int s = 0; s < 64; s++) {
            float av[4], bv[4];
#pragma unroll
            for (int i = 0; i < 4; i++) av[i] = Ss[(ty * 4 + i) * 65 + s];
#pragma unroll
            for (int jj = 0; jj < 4; jj++) bv[jj] = Vs[s * 65 + tx * 4 + jj];
#pragma unroll
            for (int i = 0; i < 4; i++)
#pragma unroll
                for (int jj = 0; jj < 4; jj++) acc[i][jj] += av[i] * bv[jj];
        }
    }

    float* Out = (MODE == 0) ? g_o2 : g_ctx;
#pragma unroll
    for (int i = 0; i < 4; i++)
#pragma unroll
        for (int jj = 0; jj < 4; jj++)
            Out[base + (size_t)(t0 + ty * 4 + i) * D_ + tx * 4 + jj] = acc[i][jj];
}

// ============================================================
// Kernel 4: per-(b,h) normalization over (t,d), scatter to (b,s,dm)
// ============================================================
__device__ __forceinline__ double warpReduceSumD(double v) {
#pragma unroll
    for (int o = 16; o > 0; o >>= 1) v += __shfl_down_sync(0xffffffffu, v, o);
    return v;
}

__global__ void __launch_bounds__(512) gn_kernel(const float* __restrict__ gn_w,
                                                 const float* __restrict__ gn_b) {
    const int bh = blockIdx.x;            // 0..31
    const int b_idx = bh / H_, h = bh % H_;
    const float* src = g_ctx + (size_t)bh * S_ * D_;
    const int N = S_ * D_;                // 131072

    double sum = 0.0, sq = 0.0;
    for (int i = threadIdx.x; i < N; i += 512) {
        const float v = src[i];
        sum += v;
        sq += (double)v * (double)v;
    }
    __shared__ double ssum[16], ssq[16];
    const int lane = threadIdx.x & 31, wid = threadIdx.x >> 5;
    sum = warpReduceSumD(sum);
    sq = warpReduceSumD(sq);
    if (lane == 0) { ssum[wid] = sum; ssq[wid] = sq; }
    __syncthreads();
    __shared__ float s_mean, s_rstd;
    if (threadIdx.x == 0) {
        double ts = 0.0, tq = 0.0;
        for (int i = 0; i < 16; i++) { ts += ssum[i]; tq += ssq[i]; }
        const double mean = ts / (double)N;
        const double var = tq / (double)N - mean * mean;
        s_mean = (float)mean;
        s_rstd = (float)rsqrt(var + 1e-5);
    }
    __syncthreads();
    const float mean = s_mean, rstd = s_rstd;
    for (int i = threadIdx.x; i < N; i += 512) {
        const int t = i >> 6, d = i & 63;
        const int col = h * D_ + d;
        g_normed[((size_t)b_idx * S_ + t) * DM_ + col] =
            (src[i] - mean) * rstd * gn_w[col] + gn_b[col];
    }
}

// ============================================================
// Kernel 5: output projection.  out[m,n] = sum_k normed[m,k]*Wout[n,k] + b[n]
// M = 4096, N = 1024, K = 1024.
// ============================================================
__global__ void __launch_bounds__(256) out_gemm_kernel(
    const float* __restrict__ Wout, const float* __restrict__ bias,
    float* __restrict__ out) {
    __shared__ float As[16][68];
    __shared__ float Bs[16][68];
    const int bm = blockIdx.y * 64;
    const int bn = blockIdx.x * 64;
    const int tid = threadIdx.x;
    const int tx = tid & 15, ty = tid >> 4;
    const int lr = tid >> 2;
    const int lc = (tid & 3) * 4;

    float acc[4][4] = {};
    for (int k0 = 0; k0 < 1024; k0 += 16) {
        float4 a = *(const float4*)&g_normed[(size_t)(bm + lr) * 1024 + k0 + lc];
        float4 b = *(const float4*)&Wout[(size_t)(bn + lr) * 1024 + k0 + lc];
        As[lc + 0][lr] = a.x; As[lc + 1][lr] = a.y;
        As[lc + 2][lr] = a.z; As[lc + 3][lr] = a.w;
        Bs[lc + 0][lr] = b.x; Bs[lc + 1][lr] = b.y;
        Bs[lc + 2][lr] = b.z; Bs[lc + 3][lr] = b.w;
        __syncthreads();
#pragma unroll
        for (int kk = 0; kk < 16; kk++) {
            float av[4], bv[4];
#pragma unroll
            for (int i = 0; i < 4; i++) av[i] = As[kk][ty * 4 + i];
#pragma unroll
            for (int j = 0; j < 4; j++) bv[j] = Bs[kk][tx * 4 + j];
#pragma unroll
            for (int i = 0; i < 4; i++)
#pragma unroll
                for (int j = 0; j < 4; j++) acc[i][j] += av[i] * bv[j];
        }
        __syncthreads();
    }
#pragma unroll
    for (int i = 0; i < 4; i++) {
        const int m = bm + ty * 4 + i;
#pragma unroll
        for (int j = 0; j < 4; j++) {
            const int n = bn + tx * 4 + j;
            out[(size_t)m * DM_ + n] = acc[i][j] + bias[n];
        }
    }
}

// ============================================================
extern "C" void kernel_launch(void* const* d_in, const int* in_sizes, int n_in,
                              void* d_out, int out_size) {
    const float* x       = (const float*)d_in[0];
    const float* Wproj_w = (const float*)d_in[1];
    const float* Wproj_b = (const float*)d_in[2];
    const float* out_w   = (const float*)d_in[3];
    const float* out_b   = (const float*)d_in[4];
    const float* gn_w    = (const float*)d_in[5];
    const float* gn_b    = (const float*)d_in[6];
    float* out = (float*)d_out;

    // opt-in >48KB dynamic smem (idempotent, not a stream op)
    cudaFuncSetAttribute(attn_kernel<0>, cudaFuncAttributeMaxDynamicSharedMemorySize, 66560);
    cudaFuncSetAttribute(attn_kernel<1>, cudaFuncAttributeMaxDynamicSharedMemorySize, 66560);

    // 1) QKV projection + scatter
    qkv_gemm_kernel<<<dim3(48, 64), 256>>>(x, Wproj_w, Wproj_b);
    // 2) pass A: o2 = causal(q,k,k)
    attn_kernel<0><<<dim3(S_ / 64, BH_), 256, 3 * 64 * 65 * 4>>>();
    // 3) pass B: ctx = causal(2q-o2, k, v)
    attn_kernel<1><<<dim3(S_ / 64, BH_), 256, 4 * 64 * 65 * 4>>>();
    // 4) per-(b,h) norm + scatter
    gn_kernel<<<BH_, 512>>>(gn_w, gn_b);
    // 5) output projection
    out_gemm_kernel<<<dim3(DM_ / 64, (B_ * S_) / 64), 256>>>(out_w, out_b, out);
}

// round 11
// speedup vs baseline: 1.0436x; 1.0436x over previous

#include <cuda_runtime.h>
#include <math.h>
#include <stdint.h>

#define B_  2
#define S_  2048
#define H_  16
#define D_  64
#define DM_ 1024
#define BH_ (B_ * H_)

// -------- scratch (device globals: allocation-free) --------
__device__ float g_q[(size_t)BH_ * S_ * D_];
__device__ float g_k[(size_t)BH_ * S_ * D_];
__device__ float g_v[(size_t)BH_ * S_ * D_];
__device__ float g_o2[(size_t)BH_ * S_ * D_];
__device__ float g_ctx[(size_t)BH_ * S_ * D_];
__device__ float g_normed[(size_t)B_ * S_ * DM_];

// ============================================================
// Kernel 1: QKV projection, 8x8 micro-tile.
// C[m,n] = sum_k x[m,k]*W[n,k] + b[n];  M=4096, N=3072, K=1024.
// Block 128x128, BK=16, 256 threads (16x16). k-major smem tiles.
// Epilogue scatters into g_q/g_k/g_v in (b,h,s,d) layout.
// ============================================================
__global__ void __launch_bounds__(256) qkv_gemm_kernel(
    const float* __restrict__ x, const float* __restrict__ W,
    const float* __restrict__ bias) {
    __shared__ float As[16][132];
    __shared__ float Bs[16][132];
    const int bm = blockIdx.y * 128;
    const int bn = blockIdx.x * 128;
    const int tid = threadIdx.x;
    const int tx = tid & 15, ty = tid >> 4;     // 16x16 thread grid
    const int lrow = tid >> 1;                  // 0..127
    const int lk = (tid & 1) * 8;               // 0 or 8

    float acc[8][8] = {};

    for (int k0 = 0; k0 < 1024; k0 += 16) {
        const float4 a0 = *(const float4*)&x[(size_t)(bm + lrow) * 1024 + k0 + lk];
        const float4 a1 = *(const float4*)&x[(size_t)(bm + lrow) * 1024 + k0 + lk + 4];
        const float4 b0 = *(const float4*)&W[(size_t)(bn + lrow) * 1024 + k0 + lk];
        const float4 b1 = *(const float4*)&W[(size_t)(bn + lrow) * 1024 + k0 + lk + 4];
        __syncthreads();
        As[lk + 0][lrow] = a0.x; As[lk + 1][lrow] = a0.y;
        As[lk + 2][lrow] = a0.z; As[lk + 3][lrow] = a0.w;
        As[lk + 4][lrow] = a1.x; As[lk + 5][lrow] = a1.y;
        As[lk + 6][lrow] = a1.z; As[lk + 7][lrow] = a1.w;
        Bs[lk + 0][lrow] = b0.x; Bs[lk + 1][lrow] = b0.y;
        Bs[lk + 2][lrow] = b0.z; Bs[lk + 3][lrow] = b0.w;
        Bs[lk + 4][lrow] = b1.x; Bs[lk + 5][lrow] = b1.y;
        Bs[lk + 6][lrow] = b1.z; Bs[lk + 7][lrow] = b1.w;
        __syncthreads();

#pragma unroll
        for (int kk = 0; kk < 16; kk++) {
            const float4 xa = *(const float4*)&As[kk][ty * 8];
            const float4 xb = *(const float4*)&As[kk][ty * 8 + 4];
            const float4 ya = *(const float4*)&Bs[kk][tx * 8];
            const float4 yb = *(const float4*)&Bs[kk][tx * 8 + 4];
            float av[8], bv[8];
            av[0] = xa.x; av[1] = xa.y; av[2] = xa.z; av[3] = xa.w;
            av[4] = xb.x; av[5] = xb.y; av[6] = xb.z; av[7] = xb.w;
            bv[0] = ya.x; bv[1] = ya.y; bv[2] = ya.z; bv[3] = ya.w;
            bv[4] = yb.x; bv[5] = yb.y; bv[6] = yb.z; bv[7] = yb.w;
#pragma unroll
            for (int i = 0; i < 8; i++)
#pragma unroll
                for (int j = 0; j < 8; j++) acc[i][j] += av[i] * bv[j];
        }
    }

    // scatter epilogue (4 consecutive n stay inside one head's d-range)
#pragma unroll
    for (int i = 0; i < 8; i++) {
        const int m = bm + ty * 8 + i;
        const int b_idx = m >> 11, s_idx = m & 2047;
#pragma unroll
        for (int jh = 0; jh < 2; jh++) {
            const int n0 = bn + tx * 8 + jh * 4;
            const float4 bb = *(const float4*)&bias[n0];
            float4 v;
            v.x = acc[i][jh * 4 + 0] + bb.x;
            v.y = acc[i][jh * 4 + 1] + bb.y;
            v.z = acc[i][jh * 4 + 2] + bb.z;
            v.w = acc[i][jh * 4 + 3] + bb.w;
            const int which = n0 >> 10;
            const int wi = n0 & 1023;
            const int h = wi >> 6, d = wi & 63;
            float* dst = (which == 0) ? g_q : (which == 1) ? g_k : g_v;
            *(float4*)&dst[(((size_t)b_idx * H_ + h) * S_ + s_idx) * D_ + d] = v;
        }
    }
}

// ============================================================
// Kernel 2/3: causal no-softmax attention pass (VERBATIM round-1).
// MODE 0: Qeff = q,        V = k,  Out = o2
// MODE 1: Qeff = 2q - o2,  V = v,  Out = ctx
// ============================================================
template <int MODE>
__global__ void __launch_bounds__(256) attn_kernel() {
    extern __shared__ float sm[];
    float* Qs = sm;                       // 64 x 65
    float* Ks = sm + 64 * 65;
    float* Ss = sm + 2 * 64 * 65;
    float* Vs = (MODE == 0) ? Ks : sm + 3 * 64 * 65;

    const int bh = blockIdx.y;
    const int qi = blockIdx.x;
    const size_t base = (size_t)bh * S_ * D_;
    const int t0 = qi * 64;
    const int tid = threadIdx.x;
    const int tx = tid & 15, ty = tid >> 4;
    const int lr = tid >> 2;              // row loader 0..63
    const int lc0 = (tid & 3) * 16;       // 16 floats per thread

    // load Q block (Qeff)
    {
        const float* qp = g_q + base + (size_t)(t0 + lr) * D_;
        const float* op = g_o2 + base + (size_t)(t0 + lr) * D_;
#pragma unroll
        for (int u = 0; u < 4; u++) {
            const int c = lc0 + u * 4;
            float4 a = *(const float4*)(qp + c);
            if (MODE == 1) {
                float4 o = *(const float4*)(op + c);
                a.x = 2.f * a.x - o.x; a.y = 2.f * a.y - o.y;
                a.z = 2.f * a.z - o.z; a.w = 2.f * a.w - o.w;
            }
            Qs[lr * 65 + c + 0] = a.x; Qs[lr * 65 + c + 1] = a.y;
            Qs[lr * 65 + c + 2] = a.z; Qs[lr * 65 + c + 3] = a.w;
        }
    }

    float acc[4][4] = {};
    for (int j = 0; j <= qi; j++) {
        const int s0 = j * 64;
        __syncthreads();   // prev iter done with Ks/Vs/Ss
        {
            const float* kp = g_k + base + (size_t)(s0 + lr) * D_;
#pragma unroll
            for (int u = 0; u < 4; u++) {
                const int c = lc0 + u * 4;
                float4 a = *(const float4*)(kp + c);
                Ks[lr * 65 + c + 0] = a.x; Ks[lr * 65 + c + 1] = a.y;
                Ks[lr * 65 + c + 2] = a.z; Ks[lr * 65 + c + 3] = a.w;
            }
            if (MODE == 1) {
                const float* vp = g_v + base + (size_t)(s0 + lr) * D_;
#pragma unroll
                for (int u = 0; u < 4; u++) {
                    const int c = lc0 + u * 4;
                    float4 a = *(const float4*)(vp + c);
                    Vs[lr * 65 + c + 0] = a.x; Vs[lr * 65 + c + 1] = a.y;
                    Vs[lr * 65 + c + 2] = a.z; Vs[lr * 65 + c + 3] = a.w;
                }
            }
        }
        __syncthreads();

        // phase 1: S = Qeff * K^T  (mask s>t; only bites on diagonal block)
        float sc[4][4] = {};
#pragma unroll 16
        for (int d = 0; d < 64; d++) {
            float av[4], bv[4];
#pragma unroll
            for (int i = 0; i < 4; i++) av[i] = Qs[(ty * 4 + i) * 65 + d];
#pragma unroll
            for (int jj = 0; jj < 4; jj++) bv[jj] = Ks[(tx * 4 + jj) * 65 + d];
#pragma unroll
            for (int i = 0; i < 4; i++)
#pragma unroll
                for (int jj = 0; jj < 4; jj++) sc[i][jj] += av[i] * bv[jj];
        }
#pragma unroll
        for (int i = 0; i < 4; i++) {
            const int tt = t0 + ty * 4 + i;
#pragma unroll
            for (int jj = 0; jj < 4; jj++) {
                const int ss = s0 + tx * 4 + jj;
                Ss[(ty * 4 + i) * 65 + tx * 4 + jj] = (ss <= tt) ? sc[i][jj] : 0.f;
            }
        }
        __syncthreads();

        // phase 2: O += S * V
#pragma unroll 16
        for (int s = 0; s < 64; s++) {
            float av[4], bv[4];
#pragma unroll
            for (int i = 0; i < 4; i++) av[i] = Ss[(ty * 4 + i) * 65 + s];
#pragma unroll
            for (int jj = 0; jj < 4; jj++) bv[jj] = Vs[s * 65 + tx * 4 + jj];
#pragma unroll
            for (int i = 0; i < 4; i++)
#pragma unroll
                for (int jj = 0; jj < 4; jj++) acc[i][jj] += av[i] * bv[jj];
        }
    }

    float* Out = (MODE == 0) ? g_o2 : g_ctx;
#pragma unroll
    for (int i = 0; i < 4; i++)
#pragma unroll
        for (int jj = 0; jj < 4; jj++)
            Out[base + (size_t)(t0 + ty * 4 + i) * D_ + tx * 4 + jj] = acc[i][jj];
}

// ============================================================
// Kernel 4: per-(b,h) normalization over (t,d), scatter to (b,s,dm)
// ============================================================
__device__ __forceinline__ double warpReduceSumD(double v) {
#pragma unroll
    for (int o = 16; o > 0; o >>= 1) v += __shfl_down_sync(0xffffffffu, v, o);
    return v;
}

__global__ void __launch_bounds__(512) gn_kernel(const float* __restrict__ gn_w,
                                                 const float* __restrict__ gn_b) {
    const int bh = blockIdx.x;            // 0..31
    const int b_idx = bh / H_, h = bh % H_;
    const float* src = g_ctx + (size_t)bh * S_ * D_;
    const int N = S_ * D_;                // 131072

    double sum = 0.0, sq = 0.0;
    for (int i = threadIdx.x; i < N; i += 512) {
        const float v = src[i];
        sum += v;
        sq += (double)v * (double)v;
    }
    __shared__ double ssum[16], ssq[16];
    const int lane = threadIdx.x & 31, wid = threadIdx.x >> 5;
    sum = warpReduceSumD(sum);
    sq = warpReduceSumD(sq);
    if (lane == 0) { ssum[wid] = sum; ssq[wid] = sq; }
    __syncthreads();
    __shared__ float s_mean, s_rstd;
    if (threadIdx.x == 0) {
        double ts = 0.0, tq = 0.0;
        for (int i = 0; i < 16; i++) { ts += ssum[i]; tq += ssq[i]; }
        const double mean = ts / (double)N;
        const double var = tq / (double)N - mean * mean;
        s_mean = (float)mean;
        s_rstd = (float)rsqrt(var + 1e-5);
    }
    __syncthreads();
    const float mean = s_mean, rstd = s_rstd;
    for (int i = threadIdx.x; i < N; i += 512) {
        const int t = i >> 6, d = i & 63;
        const int col = h * D_ + d;
        g_normed[((size_t)b_idx * S_ + t) * DM_ + col] =
            (src[i] - mean) * rstd * gn_w[col] + gn_b[col];
    }
}

// ============================================================
// Kernel 5: output projection, 8x8 micro-tile.
// out[m,n] = sum_k normed[m,k]*Wout[n,k] + b[n];  M=4096, N=1024, K=1024.
// ============================================================
__global__ void __launch_bounds__(256) out_gemm_kernel(
    const float* __restrict__ Wout, const float* __restrict__ bias,
    float* __restrict__ out) {
    __shared__ float As[16][132];
    __shared__ float Bs[16][132];
    const int bm = blockIdx.y * 128;
    const int bn = blockIdx.x * 128;
    const int tid = threadIdx.x;
    const int tx = tid & 15, ty = tid >> 4;
    const int lrow = tid >> 1;
    const int lk = (tid & 1) * 8;

    float acc[8][8] = {};

    for (int k0 = 0; k0 < 1024; k0 += 16) {
        const float4 a0 = *(const float4*)&g_normed[(size_t)(bm + lrow) * 1024 + k0 + lk];
        const float4 a1 = *(const float4*)&g_normed[(size_t)(bm + lrow) * 1024 + k0 + lk + 4];
        const float4 b0 = *(const float4*)&Wout[(size_t)(bn + lrow) * 1024 + k0 + lk];
        const float4 b1 = *(const float4*)&Wout[(size_t)(bn + lrow) * 1024 + k0 + lk + 4];
        __syncthreads();
        As[lk + 0][lrow] = a0.x; As[lk + 1][lrow] = a0.y;
        As[lk + 2][lrow] = a0.z; As[lk + 3][lrow] = a0.w;
        As[lk + 4][lrow] = a1.x; As[lk + 5][lrow] = a1.y;
        As[lk + 6][lrow] = a1.z; As[lk + 7][lrow] = a1.w;
        Bs[lk + 0][lrow] = b0.x; Bs[lk + 1][lrow] = b0.y;
        Bs[lk + 2][lrow] = b0.z; Bs[lk + 3][lrow] = b0.w;
        Bs[lk + 4][lrow] = b1.x; Bs[lk + 5][lrow] = b1.y;
        Bs[lk + 6][lrow] = b1.z; Bs[lk + 7][lrow] = b1.w;
        __syncthreads();

#pragma unroll
        for (int kk = 0; kk < 16; kk++) {
            const float4 xa = *(const float4*)&As[kk][ty * 8];
            const float4 xb = *(const float4*)&As[kk][ty * 8 + 4];
            const float4 ya = *(const float4*)&Bs[kk][tx * 8];
            const float4 yb = *(const float4*)&Bs[kk][tx * 8 + 4];
            float av[8], bv[8];
            av[0] = xa.x; av[1] = xa.y; av[2] = xa.z; av[3] = xa.w;
            av[4] = xb.x; av[5] = xb.y; av[6] = xb.z; av[7] = xb.w;
            bv[0] = ya.x; bv[1] = ya.y; bv[2] = ya.z; bv[3] = ya.w;
            bv[4] = yb.x; bv[5] = yb.y; bv[6] = yb.z; bv[7] = yb.w;
#pragma unroll
            for (int i = 0; i < 8; i++)
#pragma unroll
                for (int j = 0; j < 8; j++) acc[i][j] += av[i] * bv[j];
        }
    }

#pragma unroll
    for (int i = 0; i < 8; i++) {
        const int m = bm + ty * 8 + i;
#pragma unroll
        for (int jh = 0; jh < 2; jh++) {
            const int n0 = bn + tx * 8 + jh * 4;
            const float4 bb = *(const float4*)&bias[n0];
            float4 v;
            v.x = acc[i][jh * 4 + 0] + bb.x;
            v.y = acc[i][jh * 4 + 1] + bb.y;
            v.z = acc[i][jh * 4 + 2] + bb.z;
            v.w = acc[i][jh * 4 + 3] + bb.w;
            *(float4*)&out[(size_t)m * DM_ + n0] = v;
        }
    }
}

// ============================================================
extern "C" void kernel_launch(void* const* d_in, const int* in_sizes, int n_in,
                              void* d_out, int out_size) {
    const float* x       = (const float*)d_in[0];
    const float* Wproj_w = (const float*)d_in[1];
    const float* Wproj_b = (const float*)d_in[2];
    const float* out_w   = (const float*)d_in[3];
    const float* out_b   = (const float*)d_in[4];
    const float* gn_w    = (const float*)d_in[5];
    const float* gn_b    = (const float*)d_in[6];
    float* out = (float*)d_out;

    // opt-in >48KB dynamic smem (idempotent, not a stream op)
    cudaFuncSetAttribute(attn_kernel<0>, cudaFuncAttributeMaxDynamicSharedMemorySize, 66560);
    cudaFuncSetAttribute(attn_kernel<1>, cudaFuncAttributeMaxDynamicSharedMemorySize, 66560);

    // 1) QKV projection + scatter (128x128 tiles)
    qkv_gemm_kernel<<<dim3(24, 32), 256>>>(x, Wproj_w, Wproj_b);
    // 2) pass A: o2 = causal(q,k,k)
    attn_kernel<0><<<dim3(S_ / 64, BH_), 256, 3 * 64 * 65 * 4>>>();
    // 3) pass B: ctx = causal(2q-o2, k, v)
    attn_kernel<1><<<dim3(S_ / 64, BH_), 256, 4 * 64 * 65 * 4>>>();
    // 4) per-(b,h) norm + scatter
    gn_kernel<<<BH_, 512>>>(gn_w, gn_b);
    // 5) output projection (128x128 tiles)
    out_gemm_kernel<<<dim3(8, 32), 256>>>(out_w, out_b, out);
}

// round 12
// speedup vs baseline: 1.0743x; 1.0294x over previous

#include <cuda_runtime.h>
#include <math.h>
#include <stdint.h>

#define B_  2
#define S_  2048
#define H_  16
#define D_  64
#define DM_ 1024
#define BH_ (B_ * H_)

// -------- scratch (device globals: allocation-free) --------
__device__ float g_q[(size_t)BH_ * S_ * D_];
__device__ float g_k[(size_t)BH_ * S_ * D_];
__device__ float g_v[(size_t)BH_ * S_ * D_];
__device__ float g_o2[(size_t)BH_ * S_ * D_];
__device__ float g_ctx[(size_t)BH_ * S_ * D_];
__device__ float g_normed[(size_t)B_ * S_ * DM_];

// ============================================================
// Kernel 1: QKV projection, 8x8 micro-tile (VERBATIM round-11).
// ============================================================
__global__ void __launch_bounds__(256) qkv_gemm_kernel(
    const float* __restrict__ x, const float* __restrict__ W,
    const float* __restrict__ bias) {
    __shared__ float As[16][132];
    __shared__ float Bs[16][132];
    const int bm = blockIdx.y * 128;
    const int bn = blockIdx.x * 128;
    const int tid = threadIdx.x;
    const int tx = tid & 15, ty = tid >> 4;     // 16x16 thread grid
    const int lrow = tid >> 1;                  // 0..127
    const int lk = (tid & 1) * 8;               // 0 or 8

    float acc[8][8] = {};

    for (int k0 = 0; k0 < 1024; k0 += 16) {
        const float4 a0 = *(const float4*)&x[(size_t)(bm + lrow) * 1024 + k0 + lk];
        const float4 a1 = *(const float4*)&x[(size_t)(bm + lrow) * 1024 + k0 + lk + 4];
        const float4 b0 = *(const float4*)&W[(size_t)(bn + lrow) * 1024 + k0 + lk];
        const float4 b1 = *(const float4*)&W[(size_t)(bn + lrow) * 1024 + k0 + lk + 4];
        __syncthreads();
        As[lk + 0][lrow] = a0.x; As[lk + 1][lrow] = a0.y;
        As[lk + 2][lrow] = a0.z; As[lk + 3][lrow] = a0.w;
        As[lk + 4][lrow] = a1.x; As[lk + 5][lrow] = a1.y;
        As[lk + 6][lrow] = a1.z; As[lk + 7][lrow] = a1.w;
        Bs[lk + 0][lrow] = b0.x; Bs[lk + 1][lrow] = b0.y;
        Bs[lk + 2][lrow] = b0.z; Bs[lk + 3][lrow] = b0.w;
        Bs[lk + 4][lrow] = b1.x; Bs[lk + 5][lrow] = b1.y;
        Bs[lk + 6][lrow] = b1.z; Bs[lk + 7][lrow] = b1.w;
        __syncthreads();

#pragma unroll
        for (int kk = 0; kk < 16; kk++) {
            const float4 xa = *(const float4*)&As[kk][ty * 8];
            const float4 xb = *(const float4*)&As[kk][ty * 8 + 4];
            const float4 ya = *(const float4*)&Bs[kk][tx * 8];
            const float4 yb = *(const float4*)&Bs[kk][tx * 8 + 4];
            float av[8], bv[8];
            av[0] = xa.x; av[1] = xa.y; av[2] = xa.z; av[3] = xa.w;
            av[4] = xb.x; av[5] = xb.y; av[6] = xb.z; av[7] = xb.w;
            bv[0] = ya.x; bv[1] = ya.y; bv[2] = ya.z; bv[3] = ya.w;
            bv[4] = yb.x; bv[5] = yb.y; bv[6] = yb.z; bv[7] = yb.w;
#pragma unroll
            for (int i = 0; i < 8; i++)
#pragma unroll
                for (int j = 0; j < 8; j++) acc[i][j] += av[i] * bv[j];
        }
    }

#pragma unroll
    for (int i = 0; i < 8; i++) {
        const int m = bm + ty * 8 + i;
        const int b_idx = m >> 11, s_idx = m & 2047;
#pragma unroll
        for (int jh = 0; jh < 2; jh++) {
            const int n0 = bn + tx * 8 + jh * 4;
            const float4 bb = *(const float4*)&bias[n0];
            float4 v;
            v.x = acc[i][jh * 4 + 0] + bb.x;
            v.y = acc[i][jh * 4 + 1] + bb.y;
            v.z = acc[i][jh * 4 + 2] + bb.z;
            v.w = acc[i][jh * 4 + 3] + bb.w;
            const int which = n0 >> 10;
            const int wi = n0 & 1023;
            const int h = wi >> 6, d = wi & 63;
            float* dst = (which == 0) ? g_q : (which == 1) ? g_k : g_v;
            *(float4*)&dst[(((size_t)b_idx * H_ + h) * S_ + s_idx) * D_ + d] = v;
        }
    }
}

// ============================================================
// Kernel 2/3: causal no-softmax attention, vectorized operands.
// MODE 0: Qeff = q,        V = k,  Out = o2
// MODE 1: Qeff = 2q - o2,  V = v,  Out = ctx
// 256 threads, 64x64 tile, 4x4 micro-tile (round-1 shape).
// Qt/Kt stored d-major; S stored transposed [s][r]; V natural.
// Inner loops: 2x LDS.128 + 16 FFMA per k-step.
// ============================================================
template <int MODE>
__global__ void __launch_bounds__(256) attn_kernel() {
    extern __shared__ float sm[];
    float* Qt = sm;                   // [64][68]  Qt[d*68 + r]
    float* Kt = sm + 64 * 68;         // [64][68]  Kt[d*68 + s]
    float* St = sm + 2 * 64 * 68;     // [64][68]  St[s*68 + r]
    float* Vn = sm + 3 * 64 * 68;     // [64][68]  Vn[s*68 + d]

    const int bh = blockIdx.y;
    const int qi = gridDim.x - 1 - blockIdx.x;   // largest blocks first
    const size_t base = (size_t)bh * S_ * D_;
    const int t0 = qi * 64;
    const int tid = threadIdx.x;
    const int tx = tid & 15, ty = tid >> 4;
    const int lr = tid >> 2;              // 0..63 row loader
    const int lc0 = (tid & 3) * 16;       // 16 floats per thread

    // ---- load Q block, transposed to d-major ----
    {
        const float* qp = g_q + base + (size_t)(t0 + lr) * D_;
        const float* op = g_o2 + base + (size_t)(t0 + lr) * D_;
#pragma unroll
        for (int u = 0; u < 4; u++) {
            const int c = lc0 + u * 4;
            float4 a = *(const float4*)(qp + c);
            if (MODE == 1) {
                float4 o = *(const float4*)(op + c);
                a.x = 2.f * a.x - o.x; a.y = 2.f * a.y - o.y;
                a.z = 2.f * a.z - o.z; a.w = 2.f * a.w - o.w;
            }
            Qt[(c + 0) * 68 + lr] = a.x;
            Qt[(c + 1) * 68 + lr] = a.y;
            Qt[(c + 2) * 68 + lr] = a.z;
            Qt[(c + 3) * 68 + lr] = a.w;
        }
    }

    float acc[4][4] = {};
    for (int jb = 0; jb <= qi; jb++) {
        const int s0 = jb * 64;
        __syncthreads();   // prev iter done with Kt/Vn/St
        // ---- load K tile (d-major) + V tile (natural) ----
        {
            const float* kp = g_k + base + (size_t)(s0 + lr) * D_;
#pragma unroll
            for (int u = 0; u < 4; u++) {
                const int c = lc0 + u * 4;
                const float4 kv = *(const float4*)(kp + c);
                Kt[(c + 0) * 68 + lr] = kv.x;
                Kt[(c + 1) * 68 + lr] = kv.y;
                Kt[(c + 2) * 68 + lr] = kv.z;
                Kt[(c + 3) * 68 + lr] = kv.w;
                if (MODE == 0) {
                    *(float4*)&Vn[lr * 68 + c] = kv;
                } else {
                    *(float4*)&Vn[lr * 68 + c] =
                        *(const float4*)&g_v[base + (size_t)(s0 + lr) * D_ + c];
                }
            }
        }
        __syncthreads();

        // ---- phase 1: S = Qeff * K^T ----
        float sc[4][4] = {};
#pragma unroll 16
        for (int d = 0; d < 64; d++) {
            const float4 qa = *(const float4*)&Qt[d * 68 + ty * 4];
            const float4 ka = *(const float4*)&Kt[d * 68 + tx * 4];
            sc[0][0] += qa.x * ka.x; sc[0][1] += qa.x * ka.y;
            sc[0][2] += qa.x * ka.z; sc[0][3] += qa.x * ka.w;
            sc[1][0] += qa.y * ka.x; sc[1][1] += qa.y * ka.y;
            sc[1][2] += qa.y * ka.z; sc[1][3] += qa.y * ka.w;
            sc[2][0] += qa.z * ka.x; sc[2][1] += qa.z * ka.y;
            sc[2][2] += qa.z * ka.z; sc[2][3] += qa.z * ka.w;
            sc[3][0] += qa.w * ka.x; sc[3][1] += qa.w * ka.y;
            sc[3][2] += qa.w * ka.z; sc[3][3] += qa.w * ka.w;
        }

        // ---- causal mask (diagonal block only) ----
        if (jb == qi) {
#pragma unroll
            for (int i = 0; i < 4; i++) {
                const int t = ty * 4 + i;
#pragma unroll
                for (int j = 0; j < 4; j++) {
                    const int s = tx * 4 + j;
                    if (s > t) sc[i][j] = 0.f;
                }
            }
        }

        // ---- store S transposed [s][r] (vector stores) ----
#pragma unroll
        for (int j = 0; j < 4; j++) {
            float4 v;
            v.x = sc[0][j]; v.y = sc[1][j]; v.z = sc[2][j]; v.w = sc[3][j];
            *(float4*)&St[(tx * 4 + j) * 68 + ty * 4] = v;
        }
        __syncthreads();

        // ---- phase 2: O += S * V ----
#pragma unroll 16
        for (int s = 0; s < 64; s++) {
            const float4 sa = *(const float4*)&St[s * 68 + ty * 4];
            const float4 va = *(const float4*)&Vn[s * 68 + tx * 4];
            acc[0][0] += sa.x * va.x; acc[0][1] += sa.x * va.y;
            acc[0][2] += sa.x * va.z; acc[0][3] += sa.x * va.w;
            acc[1][0] += sa.y * va.x; acc[1][1] += sa.y * va.y;
            acc[1][2] += sa.y * va.z; acc[1][3] += sa.y * va.w;
            acc[2][0] += sa.z * va.x; acc[2][1] += sa.z * va.y;
            acc[2][2] += sa.z * va.z; acc[2][3] += sa.z * va.w;
            acc[3][0] += sa.w * va.x; acc[3][1] += sa.w * va.y;
            acc[3][2] += sa.w * va.z; acc[3][3] += sa.w * va.w;
        }
    }

    // ---- epilogue: vector stores ----
    float* Out = (MODE == 0) ? g_o2 : g_ctx;
#pragma unroll
    for (int i = 0; i < 4; i++) {
        float4 v;
        v.x = acc[i][0]; v.y = acc[i][1]; v.z = acc[i][2]; v.w = acc[i][3];
        *(float4*)&Out[base + (size_t)(t0 + ty * 4 + i) * D_ + tx * 4] = v;
    }
}

// ============================================================
// Kernel 4: per-(b,h) normalization (VERBATIM round-1)
// ============================================================
__device__ __forceinline__ double warpReduceSumD(double v) {
#pragma unroll
    for (int o = 16; o > 0; o >>= 1) v += __shfl_down_sync(0xffffffffu, v, o);
    return v;
}

__global__ void __launch_bounds__(512) gn_kernel(const float* __restrict__ gn_w,
                                                 const float* __restrict__ gn_b) {
    const int bh = blockIdx.x;            // 0..31
    const int b_idx = bh / H_, h = bh % H_;
    const float* src = g_ctx + (size_t)bh * S_ * D_;
    const int N = S_ * D_;                // 131072

    double sum = 0.0, sq = 0.0;
    for (int i = threadIdx.x; i < N; i += 512) {
        const float v = src[i];
        sum += v;
        sq += (double)v * (double)v;
    }
    __shared__ double ssum[16], ssq[16];
    const int lane = threadIdx.x & 31, wid = threadIdx.x >> 5;
    sum = warpReduceSumD(sum);
    sq = warpReduceSumD(sq);
    if (lane == 0) { ssum[wid] = sum; ssq[wid] = sq; }
    __syncthreads();
    __shared__ float s_mean, s_rstd;
    if (threadIdx.x == 0) {
        double ts = 0.0, tq = 0.0;
        for (int i = 0; i < 16; i++) { ts += ssum[i]; tq += ssq[i]; }
        const double mean = ts / (double)N;
        const double var = tq / (double)N - mean * mean;
        s_mean = (float)mean;
        s_rstd = (float)rsqrt(var + 1e-5);
    }
    __syncthreads();
    const float mean = s_mean, rstd = s_rstd;
    for (int i = threadIdx.x; i < N; i += 512) {
        const int t = i >> 6, d = i & 63;
        const int col = h * D_ + d;
        g_normed[((size_t)b_idx * S_ + t) * DM_ + col] =
            (src[i] - mean) * rstd * gn_w[col] + gn_b[col];
    }
}

// ============================================================
// Kernel 5: output projection, 8x8 micro-tile (VERBATIM round-11).
// ============================================================
__global__ void __launch_bounds__(256) out_gemm_kernel(
    const float* __restrict__ Wout, const float* __restrict__ bias,
    float* __restrict__ out) {
    __shared__ float As[16][132];
    __shared__ float Bs[16][132];
    const int bm = blockIdx.y * 128;
    const int bn = blockIdx.x * 128;
    const int tid = threadIdx.x;
    const int tx = tid & 15, ty = tid >> 4;
    const int lrow = tid >> 1;
    const int lk = (tid & 1) * 8;

    float acc[8][8] = {};

    for (int k0 = 0; k0 < 1024; k0 += 16) {
        const float4 a0 = *(const float4*)&g_normed[(size_t)(bm + lrow) * 1024 + k0 + lk];
        const float4 a1 = *(const float4*)&g_normed[(size_t)(bm + lrow) * 1024 + k0 + lk + 4];
        const float4 b0 = *(const float4*)&Wout[(size_t)(bn + lrow) * 1024 + k0 + lk];
        const float4 b1 = *(const float4*)&Wout[(size_t)(bn + lrow) * 1024 + k0 + lk + 4];
        __syncthreads();
        As[lk + 0][lrow] = a0.x; As[lk + 1][lrow] = a0.y;
        As[lk + 2][lrow] = a0.z; As[lk + 3][lrow] = a0.w;
        As[lk + 4][lrow] = a1.x; As[lk + 5][lrow] = a1.y;
        As[lk + 6][lrow] = a1.z; As[lk + 7][lrow] = a1.w;
        Bs[lk + 0][lrow] = b0.x; Bs[lk + 1][lrow] = b0.y;
        Bs[lk + 2][lrow] = b0.z; Bs[lk + 3][lrow] = b0.w;
        Bs[lk + 4][lrow] = b1.x; Bs[lk + 5][lrow] = b1.y;
        Bs[lk + 6][lrow] = b1.z; Bs[lk + 7][lrow] = b1.w;
        __syncthreads();

#pragma unroll
        for (int kk = 0; kk < 16; kk++) {
            const float4 xa = *(const float4*)&As[kk][ty * 8];
            const float4 xb = *(const float4*)&As[kk][ty * 8 + 4];
            const float4 ya = *(const float4*)&Bs[kk][tx * 8];
            const float4 yb = *(const float4*)&Bs[kk][tx * 8 + 4];
            float av[8], bv[8];
            av[0] = xa.x; av[1] = xa.y; av[2] = xa.z; av[3] = xa.w;
            av[4] = xb.x; av[5] = xb.y; av[6] = xb.z; av[7] = xb.w;
            bv[0] = ya.x; bv[1] = ya.y; bv[2] = ya.z; bv[3] = ya.w;
            bv[4] = yb.x; bv[5] = yb.y; bv[6] = yb.z; bv[7] = yb.w;
#pragma unroll
            for (int i = 0; i < 8; i++)
#pragma unroll
                for (int j = 0; j < 8; j++) acc[i][j] += av[i] * bv[j];
        }
    }

#pragma unroll
    for (int i = 0; i < 8; i++) {
        const int m = bm + ty * 8 + i;
#pragma unroll
        for (int jh = 0; jh < 2; jh++) {
            const int n0 = bn + tx * 8 + jh * 4;
            const float4 bb = *(const float4*)&bias[n0];
            float4 v;
            v.x = acc[i][jh * 4 + 0] + bb.x;
            v.y = acc[i][jh * 4 + 1] + bb.y;
            v.z = acc[i][jh * 4 + 2] + bb.z;
            v.w = acc[i][jh * 4 + 3] + bb.w;
            *(float4*)&out[(size_t)m * DM_ + n0] = v;
        }
    }
}

// ============================================================
extern "C" void kernel_launch(void* const* d_in, const int* in_sizes, int n_in,
                              void* d_out, int out_size) {
    const float* x       = (const float*)d_in[0];
    const float* Wproj_w = (const float*)d_in[1];
    const float* Wproj_b = (const float*)d_in[2];
    const float* out_w   = (const float*)d_in[3];
    const float* out_b   = (const float*)d_in[4];
    const float* gn_w    = (const float*)d_in[5];
    const float* gn_b    = (const float*)d_in[6];
    float* out = (float*)d_out;

    const int attn_smem = 4 * 64 * 68 * 4;   // 69632 B
    cudaFuncSetAttribute(attn_kernel<0>, cudaFuncAttributeMaxDynamicSharedMemorySize, attn_smem);
    cudaFuncSetAttribute(attn_kernel<1>, cudaFuncAttributeMaxDynamicSharedMemorySize, attn_smem);

    // 1) QKV projection + scatter (128x128 tiles)
    qkv_gemm_kernel<<<dim3(24, 32), 256>>>(x, Wproj_w, Wproj_b);
    // 2) pass A: o2 = causal(q,k,k)
    attn_kernel<0><<<dim3(S_ / 64, BH_), 256, attn_smem>>>();
    // 3) pass B: ctx = causal(2q-o2, k, v)
    attn_kernel<1><<<dim3(S_ / 64, BH_), 256, attn_smem>>>();
    // 4) per-(b,h) norm + scatter
    gn_kernel<<<BH_, 512>>>(gn_w, gn_b);
    // 5) output projection (128x128 tiles)
    out_gemm_kernel<<<dim3(8, 32), 256>>>(out_w, out_b, out);
}

// round 14
// speedup vs baseline: 1.2020x; 1.1189x over previous

#include <cuda_runtime.h>
#include <cuda_bf16.h>
#include <mma.h>
#include <math.h>
#include <stdint.h>

using namespace nvcuda;

#define B_  2
#define S_  2048
#define H_  16
#define D_  64
#define DM_ 1024
#define BH_ (B_ * H_)

// -------- scratch (device globals: allocation-free) --------
__device__ float g_q[(size_t)BH_ * S_ * D_];
__device__ float g_k[(size_t)BH_ * S_ * D_];
__device__ float g_v[(size_t)BH_ * S_ * D_];
__device__ float g_o2[(size_t)BH_ * S_ * D_];
__device__ float g_ctx[(size_t)BH_ * S_ * D_];
__device__ float g_normed[(size_t)B_ * S_ * DM_];

#define LDT 24   // bf16 leading dim (48 bytes, multiple of 16B)

// ============================================================
// Kernel 1: QKV projection via WMMA bf16 hi/lo (3-term split).
// C[m,n] = sum_k x[m,k]*W[n,k] + b[n];  M=4096, N=3072, K=1024.
// Block 128x128, BK=16, 256 threads = 8 warps (2x4), warp 64x32.
// Epilogue scatters into g_q/g_k/g_v in (b,h,s,d) layout.
// ============================================================
__global__ void __launch_bounds__(256) qkv_wmma_kernel(
    const float* __restrict__ x, const float* __restrict__ W,
    const float* __restrict__ bias) {
    __shared__ __nv_bfloat16 Ah[128 * LDT], Al[128 * LDT];
    __shared__ __nv_bfloat16 Bh[128 * LDT], Bl[128 * LDT];
    __shared__ float stage[8][256];

    const int bm = blockIdx.y * 128, bn = blockIdx.x * 128;
    const int tid = threadIdx.x;
    const int warp = tid >> 5, lane = tid & 31;
    const int wm = warp >> 2, wn = warp & 3;     // 2x4 warp grid
    const int lrow = tid >> 1;                   // 0..127
    const int lk = (tid & 1) * 8;                // 0 or 8

    wmma::fragment<wmma::accumulator, 16, 16, 16, float> c[4][2];
#pragma unroll
    for (int i = 0; i < 4; i++)
#pragma unroll
        for (int j = 0; j < 2; j++) wmma::fill_fragment(c[i][j], 0.f);

    for (int k0 = 0; k0 < 1024; k0 += 16) {
        const float4 a0 = *(const float4*)&x[(size_t)(bm + lrow) * 1024 + k0 + lk];
        const float4 a1 = *(const float4*)&x[(size_t)(bm + lrow) * 1024 + k0 + lk + 4];
        const float4 b0 = *(const float4*)&W[(size_t)(bn + lrow) * 1024 + k0 + lk];
        const float4 b1 = *(const float4*)&W[(size_t)(bn + lrow) * 1024 + k0 + lk + 4];
        __syncthreads();
        {
            float av[8] = {a0.x, a0.y, a0.z, a0.w, a1.x, a1.y, a1.z, a1.w};
            float bv[8] = {b0.x, b0.y, b0.z, b0.w, b1.x, b1.y, b1.z, b1.w};
#pragma unroll
            for (int u = 0; u < 8; u++) {
                const __nv_bfloat16 h = __float2bfloat16(av[u]);
                Ah[lrow * LDT + lk + u] = h;
                Al[lrow * LDT + lk + u] = __float2bfloat16(av[u] - __bfloat162float(h));
                const __nv_bfloat16 g = __float2bfloat16(bv[u]);
                Bh[lrow * LDT + lk + u] = g;
                Bl[lrow * LDT + lk + u] = __float2bfloat16(bv[u] - __bfloat162float(g));
            }
        }
        __syncthreads();

        wmma::fragment<wmma::matrix_a, 16, 16, 16, __nv_bfloat16, wmma::row_major> a_h[4], a_l[4];
#pragma unroll
        for (int i = 0; i < 4; i++) {
            wmma::load_matrix_sync(a_h[i], &Ah[(wm * 64 + i * 16) * LDT], LDT);
            wmma::load_matrix_sync(a_l[i], &Al[(wm * 64 + i * 16) * LDT], LDT);
        }
#pragma unroll
        for (int j = 0; j < 2; j++) {
            wmma::fragment<wmma::matrix_b, 16, 16, 16, __nv_bfloat16, wmma::col_major> b_h, b_l;
            wmma::load_matrix_sync(b_h, &Bh[(wn * 32 + j * 16) * LDT], LDT);
            wmma::load_matrix_sync(b_l, &Bl[(wn * 32 + j * 16) * LDT], LDT);
#pragma unroll
            for (int i = 0; i < 4; i++) {
                wmma::mma_sync(c[i][j], a_h[i], b_h, c[i][j]);
                wmma::mma_sync(c[i][j], a_h[i], b_l, c[i][j]);
                wmma::mma_sync(c[i][j], a_l[i], b_h, c[i][j]);
            }
        }
    }

    // epilogue: per-tile stage -> +bias -> scatter
    const int r = lane >> 1;            // 0..15
    const int c0 = (lane & 1) * 8;      // 0 or 8
#pragma unroll
    for (int i = 0; i < 4; i++) {
#pragma unroll
        for (int j = 0; j < 2; j++) {
            wmma::store_matrix_sync(stage[warp], c[i][j], 16, wmma::mem_row_major);
            __syncwarp();
            const int m = bm + wm * 64 + i * 16 + r;
            const int b_idx = m >> 11, s_idx = m & 2047;
#pragma unroll
            for (int u = 0; u < 2; u++) {
                const int n = bn + wn * 32 + j * 16 + c0 + u * 4;
                const float4 bb = *(const float4*)&bias[n];
                float4 v;
                v.x = stage[warp][r * 16 + c0 + u * 4 + 0] + bb.x;
                v.y = stage[warp][r * 16 + c0 + u * 4 + 1] + bb.y;
                v.z = stage[warp][r * 16 + c0 + u * 4 + 2] + bb.z;
                v.w = stage[warp][r * 16 + c0 + u * 4 + 3] + bb.w;
                const int which = n >> 10;
                const int wi = n & 1023;
                const int h = wi >> 6, d = wi & 63;
                float* dst = (which == 0) ? g_q : (which == 1) ? g_k : g_v;
                *(float4*)&dst[(((size_t)b_idx * H_ + h) * S_ + s_idx) * D_ + d] = v;
            }
            __syncwarp();
        }
    }
}

// ============================================================
// Kernel 5: output projection via WMMA bf16 hi/lo.
// out[m,n] = sum_k normed[m,k]*Wout[n,k] + b[n];  M=4096, N=1024.
// ============================================================
__global__ void __launch_bounds__(256) out_wmma_kernel(
    const float* __restrict__ Wout, const float* __restrict__ bias,
    float* __restrict__ out) {
    __shared__ __nv_bfloat16 Ah[128 * LDT], Al[128 * LDT];
    __shared__ __nv_bfloat16 Bh[128 * LDT], Bl[128 * LDT];
    __shared__ float stage[8][256];

    const int bm = blockIdx.y * 128, bn = blockIdx.x * 128;
    const int tid = threadIdx.x;
    const int warp = tid >> 5, lane = tid & 31;
    const int wm = warp >> 2, wn = warp & 3;
    const int lrow = tid >> 1;
    const int lk = (tid & 1) * 8;

    wmma::fragment<wmma::accumulator, 16, 16, 16, float> c[4][2];
#pragma unroll
    for (int i = 0; i < 4; i++)
#pragma unroll
        for (int j = 0; j < 2; j++) wmma::fill_fragment(c[i][j], 0.f);

    for (int k0 = 0; k0 < 1024; k0 += 16) {
        const float4 a0 = *(const float4*)&g_normed[(size_t)(bm + lrow) * 1024 + k0 + lk];
        const float4 a1 = *(const float4*)&g_normed[(size_t)(bm + lrow) * 1024 + k0 + lk + 4];
        const float4 b0 = *(const float4*)&Wout[(size_t)(bn + lrow) * 1024 + k0 + lk];
        const float4 b1 = *(const float4*)&Wout[(size_t)(bn + lrow) * 1024 + k0 + lk + 4];
        __syncthreads();
        {
            float av[8] = {a0.x, a0.y, a0.z, a0.w, a1.x, a1.y, a1.z, a1.w};
            float bv[8] = {b0.x, b0.y, b0.z, b0.w, b1.x, b1.y, b1.z, b1.w};
#pragma unroll
            for (int u = 0; u < 8; u++) {
                const __nv_bfloat16 h = __float2bfloat16(av[u]);
                Ah[lrow * LDT + lk + u] = h;
                Al[lrow * LDT + lk + u] = __float2bfloat16(av[u] - __bfloat162float(h));
                const __nv_bfloat16 g = __float2bfloat16(bv[u]);
                Bh[lrow * LDT + lk + u] = g;
                Bl[lrow * LDT + lk + u] = __float2bfloat16(bv[u] - __bfloat162float(g));
            }
        }
        __syncthreads();

        wmma::fragment<wmma::matrix_a, 16, 16, 16, __nv_bfloat16, wmma::row_major> a_h[4], a_l[4];
#pragma unroll
        for (int i = 0; i < 4; i++) {
            wmma::load_matrix_sync(a_h[i], &Ah[(wm * 64 + i * 16) * LDT], LDT);
            wmma::load_matrix_sync(a_l[i], &Al[(wm * 64 + i * 16) * LDT], LDT);
        }
#pragma unroll
        for (int j = 0; j < 2; j++) {
            wmma::fragment<wmma::matrix_b, 16, 16, 16, __nv_bfloat16, wmma::col_major> b_h, b_l;
            wmma::load_matrix_sync(b_h, &Bh[(wn * 32 + j * 16) * LDT], LDT);
            wmma::load_matrix_sync(b_l, &Bl[(wn * 32 + j * 16) * LDT], LDT);
#pragma unroll
            for (int i = 0; i < 4; i++) {
                wmma::mma_sync(c[i][j], a_h[i], b_h, c[i][j]);
                wmma::mma_sync(c[i][j], a_h[i], b_l, c[i][j]);
                wmma::mma_sync(c[i][j], a_l[i], b_h, c[i][j]);
            }
        }
    }

    const int r = lane >> 1;
    const int c0 = (lane & 1) * 8;
#pragma unroll
    for (int i = 0; i < 4; i++) {
#pragma unroll
        for (int j = 0; j < 2; j++) {
            wmma::store_matrix_sync(stage[warp], c[i][j], 16, wmma::mem_row_major);
            __syncwarp();
            const int m = bm + wm * 64 + i * 16 + r;
#pragma unroll
            for (int u = 0; u < 2; u++) {
                const int n = bn + wn * 32 + j * 16 + c0 + u * 4;
                const float4 bb = *(const float4*)&bias[n];
                float4 v;
                v.x = stage[warp][r * 16 + c0 + u * 4 + 0] + bb.x;
                v.y = stage[warp][r * 16 + c0 + u * 4 + 1] + bb.y;
                v.z = stage[warp][r * 16 + c0 + u * 4 + 2] + bb.z;
                v.w = stage[warp][r * 16 + c0 + u * 4 + 3] + bb.w;
                *(float4*)&out[(size_t)m * DM_ + n] = v;
            }
            __syncwarp();
        }
    }
}

// ============================================================
// Kernel 2/3: causal no-softmax attention (VERBATIM round-12).
// MODE 0: Qeff = q,        V = k,  Out = o2
// MODE 1: Qeff = 2q - o2,  V = v,  Out = ctx
// ============================================================
template <int MODE>
__global__ void __launch_bounds__(256) attn_kernel() {
    extern __shared__ float sm[];
    float* Qt = sm;                   // [64][68]  Qt[d*68 + r]
    float* Kt = sm + 64 * 68;         // [64][68]  Kt[d*68 + s]
    float* St = sm + 2 * 64 * 68;     // [64][68]  St[s*68 + r]
    float* Vn = sm + 3 * 64 * 68;     // [64][68]  Vn[s*68 + d]

    const int bh = blockIdx.y;
    const int qi = gridDim.x - 1 - blockIdx.x;   // largest blocks first
    const size_t base = (size_t)bh * S_ * D_;
    const int t0 = qi * 64;
    const int tid = threadIdx.x;
    const int tx = tid & 15, ty = tid >> 4;
    const int lr = tid >> 2;              // 0..63 row loader
    const int lc0 = (tid & 3) * 16;       // 16 floats per thread

    // ---- load Q block, transposed to d-major ----
    {
        const float* qp = g_q + base + (size_t)(t0 + lr) * D_;
        const float* op = g_o2 + base + (size_t)(t0 + lr) * D_;
#pragma unroll
        for (int u = 0; u < 4; u++) {
            const int c = lc0 + u * 4;
            float4 a = *(const float4*)(qp + c);
            if (MODE == 1) {
                float4 o = *(const float4*)(op + c);
                a.x = 2.f * a.x - o.x; a.y = 2.f * a.y - o.y;
                a.z = 2.f * a.z - o.z; a.w = 2.f * a.w - o.w;
            }
            Qt[(c + 0) * 68 + lr] = a.x;
            Qt[(c + 1) * 68 + lr] = a.y;
            Qt[(c + 2) * 68 + lr] = a.z;
            Qt[(c + 3) * 68 + lr] = a.w;
        }
    }

    float acc[4][4] = {};
    for (int jb = 0; jb <= qi; jb++) {
        const int s0 = jb * 64;
        __syncthreads();   // prev iter done with Kt/Vn/St
        // ---- load K tile (d-major) + V tile (natural) ----
        {
            const float* kp = g_k + base + (size_t)(s0 + lr) * D_;
#pragma unroll
            for (int u = 0; u < 4; u++) {
                const int c = lc0 + u * 4;
                const float4 kv = *(const float4*)(kp + c);
                Kt[(c + 0) * 68 + lr] = kv.x;
                Kt[(c + 1) * 68 + lr] = kv.y;
                Kt[(c + 2) * 68 + lr] = kv.z;
                Kt[(c + 3) * 68 + lr] = kv.w;
                if (MODE == 0) {
                    *(float4*)&Vn[lr * 68 + c] = kv;
                } else {
                    *(float4*)&Vn[lr * 68 + c] =
                        *(const float4*)&g_v[base + (size_t)(s0 + lr) * D_ + c];
                }
            }
        }
        __syncthreads();

        // ---- phase 1: S = Qeff * K^T ----
        float sc[4][4] = {};
#pragma unroll 16
        for (int d = 0; d < 64; d++) {
            const float4 qa = *(const float4*)&Qt[d * 68 + ty * 4];
            const float4 ka = *(const float4*)&Kt[d * 68 + tx * 4];
            sc[0][0] += qa.x * ka.x; sc[0][1] += qa.x * ka.y;
            sc[0][2] += qa.x * ka.z; sc[0][3] += qa.x * ka.w;
            sc[1][0] += qa.y * ka.x; sc[1][1] += qa.y * ka.y;
            sc[1][2] += qa.y * ka.z; sc[1][3] += qa.y * ka.w;
            sc[2][0] += qa.z * ka.x; sc[2][1] += qa.z * ka.y;
            sc[2][2] += qa.z * ka.z; sc[2][3] += qa.z * ka.w;
            sc[3][0] += qa.w * ka.x; sc[3][1] += qa.w * ka.y;
            sc[3][2] += qa.w * ka.z; sc[3][3] += qa.w * ka.w;
        }

        // ---- causal mask (diagonal block only) ----
        if (jb == qi) {
#pragma unroll
            for (int i = 0; i < 4; i++) {
                const int t = ty * 4 + i;
#pragma unroll
                for (int j = 0; j < 4; j++) {
                    const int s = tx * 4 + j;
                    if (s > t) sc[i][j] = 0.f;
                }
            }
        }

        // ---- store S transposed [s][r] (vector stores) ----
#pragma unroll
        for (int j = 0; j < 4; j++) {
            float4 v;
            v.x = sc[0][j]; v.y = sc[1][j]; v.z = sc[2][j]; v.w = sc[3][j];
            *(float4*)&St[(tx * 4 + j) * 68 + ty * 4] = v;
        }
        __syncthreads();

        // ---- phase 2: O += S * V ----
#pragma unroll 16
        for (int s = 0; s < 64; s++) {
            const float4 sa = *(const float4*)&St[s * 68 + ty * 4];
            const float4 va = *(const float4*)&Vn[s * 68 + tx * 4];
            acc[0][0] += sa.x * va.x; acc[0][1] += sa.x * va.y;
            acc[0][2] += sa.x * va.z; acc[0][3] += sa.x * va.w;
            acc[1][0] += sa.y * va.x; acc[1][1] += sa.y * va.y;
            acc[1][2] += sa.y * va.z; acc[1][3] += sa.y * va.w;
            acc[2][0] += sa.z * va.x; acc[2][1] += sa.z * va.y;
            acc[2][2] += sa.z * va.z; acc[2][3] += sa.z * va.w;
            acc[3][0] += sa.w * va.x; acc[3][1] += sa.w * va.y;
            acc[3][2] += sa.w * va.z; acc[3][3] += sa.w * va.w;
        }
    }

    // ---- epilogue: vector stores ----
    float* Out = (MODE == 0) ? g_o2 : g_ctx;
#pragma unroll
    for (int i = 0; i < 4; i++) {
        float4 v;
        v.x = acc[i][0]; v.y = acc[i][1]; v.z = acc[i][2]; v.w = acc[i][3];
        *(float4*)&Out[base + (size_t)(t0 + ty * 4 + i) * D_ + tx * 4] = v;
    }
}

// ============================================================
// Kernel 4: per-(b,h) normalization (VERBATIM round-1)
// ============================================================
__device__ __forceinline__ double warpReduceSumD(double v) {
#pragma unroll
    for (int o = 16; o > 0; o >>= 1) v += __shfl_down_sync(0xffffffffu, v, o);
    return v;
}

__global__ void __launch_bounds__(512) gn_kernel(const float* __restrict__ gn_w,
                                                 const float* __restrict__ gn_b) {
    const int bh = blockIdx.x;            // 0..31
    const int b_idx = bh / H_, h = bh % H_;
    const float* src = g_ctx + (size_t)bh * S_ * D_;
    const int N = S_ * D_;                // 131072

    double sum = 0.0, sq = 0.0;
    for (int i = threadIdx.x; i < N; i += 512) {
        const float v = src[i];
        sum += v;
        sq += (double)v * (double)v;
    }
    __shared__ double ssum[16], ssq[16];
    const int lane = threadIdx.x & 31, wid = threadIdx.x >> 5;
    sum = warpReduceSumD(sum);
    sq = warpReduceSumD(sq);
    if (lane == 0) { ssum[wid] = sum; ssq[wid] = sq; }
    __syncthreads();
    __shared__ float s_mean, s_rstd;
    if (threadIdx.x == 0) {
        double ts = 0.0, tq = 0.0;
        for (int i = 0; i < 16; i++) { ts += ssum[i]; tq += ssq[i]; }
        const double mean = ts / (double)N;
        const double var = tq / (double)N - mean * mean;
        s_mean = (float)mean;
        s_rstd = (float)rsqrt(var + 1e-5);
    }
    __syncthreads();
    const float mean = s_mean, rstd = s_rstd;
    for (int i = threadIdx.x; i < N; i += 512) {
        const int t = i >> 6, d = i & 63;
        const int col = h * D_ + d;
        g_normed[((size_t)b_idx * S_ + t) * DM_ + col] =
            (src[i] - mean) * rstd * gn_w[col] + gn_b[col];
    }
}

// ============================================================
extern "C" void kernel_launch(void* const* d_in, const int* in_sizes, int n_in,
                              void* d_out, int out_size) {
    const float* x       = (const float*)d_in[0];
    const float* Wproj_w = (const float*)d_in[1];
    const float* Wproj_b = (const float*)d_in[2];
    const float* out_w   = (const float*)d_in[3];
    const float* out_b   = (const float*)d_in[4];
    const float* gn_w    = (const float*)d_in[5];
    const float* gn_b    = (const float*)d_in[6];
    float* out = (float*)d_out;

    const int attn_smem = 4 * 64 * 68 * 4;   // 69632 B
    cudaFuncSetAttribute(attn_kernel<0>, cudaFuncAttributeMaxDynamicSharedMemorySize, attn_smem);
    cudaFuncSetAttribute(attn_kernel<1>, cudaFuncAttributeMaxDynamicSharedMemorySize, attn_smem);

    // 1) QKV projection + scatter — WMMA bf16 hi/lo
    qkv_wmma_kernel<<<dim3(24, 32), 256>>>(x, Wproj_w, Wproj_b);
    // 2) pass A: o2 = causal(q,k,k) — FFMA (round-12)
    attn_kernel<0><<<dim3(S_ / 64, BH_), 256, attn_smem>>>();
    // 3) pass B: ctx = causal(2q-o2, k, v) — FFMA (round-12)
    attn_kernel<1><<<dim3(S_ / 64, BH_), 256, attn_smem>>>();
    // 4) per-(b,h) norm + scatter
    gn_kernel<<<BH_, 512>>>(gn_w, gn_b);
    // 5) output projection — WMMA bf16 hi/lo
    out_wmma_kernel<<<dim3(8, 32), 256>>>(out_w, out_b, out);
}

// round 15
// speedup vs baseline: 1.4181x; 1.1798x over previous

#include <cuda_runtime.h>
#include <cuda_bf16.h>
#include <mma.h>
#include <math.h>
#include <stdint.h>

using namespace nvcuda;

#define B_  2
#define S_  2048
#define H_  16
#define D_  64
#define DM_ 1024
#define BH_ (B_ * H_)

// -------- scratch (device globals: allocation-free) --------
__device__ float g_q[(size_t)BH_ * S_ * D_];
__device__ float g_k[(size_t)BH_ * S_ * D_];
__device__ float g_v[(size_t)BH_ * S_ * D_];
__device__ float g_o2[(size_t)BH_ * S_ * D_];
__device__ float g_ctx[(size_t)BH_ * S_ * D_];
__device__ float g_normed[(size_t)B_ * S_ * DM_];

#define LDT 24   // bf16 leading dim for GEMM tiles (48B, multiple of 16B)

// ============================================================
// Kernel 1: QKV projection via WMMA bf16 hi/lo (VERBATIM round-14).
// ============================================================
__global__ void __launch_bounds__(256) qkv_wmma_kernel(
    const float* __restrict__ x, const float* __restrict__ W,
    const float* __restrict__ bias) {
    __shared__ __nv_bfloat16 Ah[128 * LDT], Al[128 * LDT];
    __shared__ __nv_bfloat16 Bh[128 * LDT], Bl[128 * LDT];
    __shared__ float stage[8][256];

    const int bm = blockIdx.y * 128, bn = blockIdx.x * 128;
    const int tid = threadIdx.x;
    const int warp = tid >> 5, lane = tid & 31;
    const int wm = warp >> 2, wn = warp & 3;     // 2x4 warp grid
    const int lrow = tid >> 1;                   // 0..127
    const int lk = (tid & 1) * 8;                // 0 or 8

    wmma::fragment<wmma::accumulator, 16, 16, 16, float> c[4][2];
#pragma unroll
    for (int i = 0; i < 4; i++)
#pragma unroll
        for (int j = 0; j < 2; j++) wmma::fill_fragment(c[i][j], 0.f);

    for (int k0 = 0; k0 < 1024; k0 += 16) {
        const float4 a0 = *(const float4*)&x[(size_t)(bm + lrow) * 1024 + k0 + lk];
        const float4 a1 = *(const float4*)&x[(size_t)(bm + lrow) * 1024 + k0 + lk + 4];
        const float4 b0 = *(const float4*)&W[(size_t)(bn + lrow) * 1024 + k0 + lk];
        const float4 b1 = *(const float4*)&W[(size_t)(bn + lrow) * 1024 + k0 + lk + 4];
        __syncthreads();
        {
            float av[8] = {a0.x, a0.y, a0.z, a0.w, a1.x, a1.y, a1.z, a1.w};
            float bv[8] = {b0.x, b0.y, b0.z, b0.w, b1.x, b1.y, b1.z, b1.w};
#pragma unroll
            for (int u = 0; u < 8; u++) {
                const __nv_bfloat16 h = __float2bfloat16(av[u]);
                Ah[lrow * LDT + lk + u] = h;
                Al[lrow * LDT + lk + u] = __float2bfloat16(av[u] - __bfloat162float(h));
                const __nv_bfloat16 g = __float2bfloat16(bv[u]);
                Bh[lrow * LDT + lk + u] = g;
                Bl[lrow * LDT + lk + u] = __float2bfloat16(bv[u] - __bfloat162float(g));
            }
        }
        __syncthreads();

        wmma::fragment<wmma::matrix_a, 16, 16, 16, __nv_bfloat16, wmma::row_major> a_h[4], a_l[4];
#pragma unroll
        for (int i = 0; i < 4; i++) {
            wmma::load_matrix_sync(a_h[i], &Ah[(wm * 64 + i * 16) * LDT], LDT);
            wmma::load_matrix_sync(a_l[i], &Al[(wm * 64 + i * 16) * LDT], LDT);
        }
#pragma unroll
        for (int j = 0; j < 2; j++) {
            wmma::fragment<wmma::matrix_b, 16, 16, 16, __nv_bfloat16, wmma::col_major> b_h, b_l;
            wmma::load_matrix_sync(b_h, &Bh[(wn * 32 + j * 16) * LDT], LDT);
            wmma::load_matrix_sync(b_l, &Bl[(wn * 32 + j * 16) * LDT], LDT);
#pragma unroll
            for (int i = 0; i < 4; i++) {
                wmma::mma_sync(c[i][j], a_h[i], b_h, c[i][j]);
                wmma::mma_sync(c[i][j], a_h[i], b_l, c[i][j]);
                wmma::mma_sync(c[i][j], a_l[i], b_h, c[i][j]);
            }
        }
    }

    const int r = lane >> 1;            // 0..15
    const int c0 = (lane & 1) * 8;      // 0 or 8
#pragma unroll
    for (int i = 0; i < 4; i++) {
#pragma unroll
        for (int j = 0; j < 2; j++) {
            wmma::store_matrix_sync(stage[warp], c[i][j], 16, wmma::mem_row_major);
            __syncwarp();
            const int m = bm + wm * 64 + i * 16 + r;
            const int b_idx = m >> 11, s_idx = m & 2047;
#pragma unroll
            for (int u = 0; u < 2; u++) {
                const int n = bn + wn * 32 + j * 16 + c0 + u * 4;
                const float4 bb = *(const float4*)&bias[n];
                float4 v;
                v.x = stage[warp][r * 16 + c0 + u * 4 + 0] + bb.x;
                v.y = stage[warp][r * 16 + c0 + u * 4 + 1] + bb.y;
                v.z = stage[warp][r * 16 + c0 + u * 4 + 2] + bb.z;
                v.w = stage[warp][r * 16 + c0 + u * 4 + 3] + bb.w;
                const int which = n >> 10;
                const int wi = n & 1023;
                const int h = wi >> 6, d = wi & 63;
                float* dst = (which == 0) ? g_q : (which == 1) ? g_k : g_v;
                *(float4*)&dst[(((size_t)b_idx * H_ + h) * S_ + s_idx) * D_ + d] = v;
            }
            __syncwarp();
        }
    }
}

// ============================================================
// Kernel 5: output projection via WMMA bf16 hi/lo (VERBATIM round-14).
// ============================================================
__global__ void __launch_bounds__(256) out_wmma_kernel(
    const float* __restrict__ Wout, const float* __restrict__ bias,
    float* __restrict__ out) {
    __shared__ __nv_bfloat16 Ah[128 * LDT], Al[128 * LDT];
    __shared__ __nv_bfloat16 Bh[128 * LDT], Bl[128 * LDT];
    __shared__ float stage[8][256];

    const int bm = blockIdx.y * 128, bn = blockIdx.x * 128;
    const int tid = threadIdx.x;
    const int warp = tid >> 5, lane = tid & 31;
    const int wm = warp >> 2, wn = warp & 3;
    const int lrow = tid >> 1;
    const int lk = (tid & 1) * 8;

    wmma::fragment<wmma::accumulator, 16, 16, 16, float> c[4][2];
#pragma unroll
    for (int i = 0; i < 4; i++)
#pragma unroll
        for (int j = 0; j < 2; j++) wmma::fill_fragment(c[i][j], 0.f);

    for (int k0 = 0; k0 < 1024; k0 += 16) {
        const float4 a0 = *(const float4*)&g_normed[(size_t)(bm + lrow) * 1024 + k0 + lk];
        const float4 a1 = *(const float4*)&g_normed[(size_t)(bm + lrow) * 1024 + k0 + lk + 4];
        const float4 b0 = *(const float4*)&Wout[(size_t)(bn + lrow) * 1024 + k0 + lk];
        const float4 b1 = *(const float4*)&Wout[(size_t)(bn + lrow) * 1024 + k0 + lk + 4];
        __syncthreads();
        {
            float av[8] = {a0.x, a0.y, a0.z, a0.w, a1.x, a1.y, a1.z, a1.w};
            float bv[8] = {b0.x, b0.y, b0.z, b0.w, b1.x, b1.y, b1.z, b1.w};
#pragma unroll
            for (int u = 0; u < 8; u++) {
                const __nv_bfloat16 h = __float2bfloat16(av[u]);
                Ah[lrow * LDT + lk + u] = h;
                Al[lrow * LDT + lk + u] = __float2bfloat16(av[u] - __bfloat162float(h));
                const __nv_bfloat16 g = __float2bfloat16(bv[u]);
                Bh[lrow * LDT + lk + u] = g;
                Bl[lrow * LDT + lk + u] = __float2bfloat16(bv[u] - __bfloat162float(g));
            }
        }
        __syncthreads();

        wmma::fragment<wmma::matrix_a, 16, 16, 16, __nv_bfloat16, wmma::row_major> a_h[4], a_l[4];
#pragma unroll
        for (int i = 0; i < 4; i++) {
            wmma::load_matrix_sync(a_h[i], &Ah[(wm * 64 + i * 16) * LDT], LDT);
            wmma::load_matrix_sync(a_l[i], &Al[(wm * 64 + i * 16) * LDT], LDT);
        }
#pragma unroll
        for (int j = 0; j < 2; j++) {
            wmma::fragment<wmma::matrix_b, 16, 16, 16, __nv_bfloat16, wmma::col_major> b_h, b_l;
            wmma::load_matrix_sync(b_h, &Bh[(wn * 32 + j * 16) * LDT], LDT);
            wmma::load_matrix_sync(b_l, &Bl[(wn * 32 + j * 16) * LDT], LDT);
#pragma unroll
            for (int i = 0; i < 4; i++) {
                wmma::mma_sync(c[i][j], a_h[i], b_h, c[i][j]);
                wmma::mma_sync(c[i][j], a_h[i], b_l, c[i][j]);
                wmma::mma_sync(c[i][j], a_l[i], b_h, c[i][j]);
            }
        }
    }

    const int r = lane >> 1;
    const int c0 = (lane & 1) * 8;
#pragma unroll
    for (int i = 0; i < 4; i++) {
#pragma unroll
        for (int j = 0; j < 2; j++) {
            wmma::store_matrix_sync(stage[warp], c[i][j], 16, wmma::mem_row_major);
            __syncwarp();
            const int m = bm + wm * 64 + i * 16 + r;
#pragma unroll
            for (int u = 0; u < 2; u++) {
                const int n = bn + wn * 32 + j * 16 + c0 + u * 4;
                const float4 bb = *(const float4*)&bias[n];
                float4 v;
                v.x = stage[warp][r * 16 + c0 + u * 4 + 0] + bb.x;
                v.y = stage[warp][r * 16 + c0 + u * 4 + 1] + bb.y;
                v.z = stage[warp][r * 16 + c0 + u * 4 + 2] + bb.z;
                v.w = stage[warp][r * 16 + c0 + u * 4 + 3] + bb.w;
                *(float4*)&out[(size_t)m * DM_ + n] = v;
            }
            __syncwarp();
        }
    }
}

// ============================================================
// Kernel 2/3: causal no-softmax attention via WMMA bf16 hi/lo.
// MODE 0: Qeff = q,       V = k (reuses K tiles),  Out = o2
// MODE 1: Qeff = 2q - o2, V = v,                   Out = ctx
// 128 threads (4 warps); warp w owns 16 query rows. 64x64 tiles.
// Phase 1: S = Qeff*K^T  (K rows [s][d] = col_major B)
// Phase 2: O += S*V      (V rows [s][d] = row_major B)
// S staged -> masked -> split to bf16 hi/lo each key block.
// ============================================================
#define LDA 72   // bf16 leading dim for attention tiles
#define TSZ (64 * LDA)

template <int MODE>
__global__ void __launch_bounds__(128) attn_wmma_kernel() {
    extern __shared__ __nv_bfloat16 smb[];
    __nv_bfloat16* Qh = smb;
    __nv_bfloat16* Ql = smb + TSZ;
    __nv_bfloat16* Kh = smb + 2 * TSZ;
    __nv_bfloat16* Kl = smb + 3 * TSZ;
    __nv_bfloat16* Sh = smb + 4 * TSZ;
    __nv_bfloat16* Sl = smb + 5 * TSZ;
    __nv_bfloat16* Vh = (MODE == 0) ? Kh : smb + 6 * TSZ;
    __nv_bfloat16* Vl = (MODE == 0) ? Kl : smb + 7 * TSZ;
    float* St = (float*)(smb + ((MODE == 0) ? 6 : 8) * TSZ);   // [64][72] float

    const int bh = blockIdx.y;
    const int qi = gridDim.x - 1 - blockIdx.x;   // largest blocks first
    const size_t base = (size_t)bh * S_ * D_;
    const int t0 = qi * 64;
    const int tid = threadIdx.x;
    const int w = tid >> 5;
    const int r = tid >> 1;              // 0..63 (row for loads/converts)
    const int c0 = (tid & 1) * 32;       // 0 or 32

    // ---- load Q (Qeff), split hi/lo ----
    {
        const float* qp = g_q + base + (size_t)(t0 + r) * D_ + c0;
        const float* op = g_o2 + base + (size_t)(t0 + r) * D_ + c0;
#pragma unroll
        for (int u = 0; u < 8; u++) {
            float4 a = *(const float4*)(qp + u * 4);
            if (MODE == 1) {
                float4 o = *(const float4*)(op + u * 4);
                a.x = 2.f * a.x - o.x; a.y = 2.f * a.y - o.y;
                a.z = 2.f * a.z - o.z; a.w = 2.f * a.w - o.w;
            }
            float av[4] = {a.x, a.y, a.z, a.w};
#pragma unroll
            for (int e = 0; e < 4; e++) {
                const __nv_bfloat16 h = __float2bfloat16(av[e]);
                Qh[r * LDA + c0 + u * 4 + e] = h;
                Ql[r * LDA + c0 + u * 4 + e] = __float2bfloat16(av[e] - __bfloat162float(h));
            }
        }
    }

    wmma::fragment<wmma::accumulator, 16, 16, 16, float> accO[4];
#pragma unroll
    for (int j = 0; j < 4; j++) wmma::fill_fragment(accO[j], 0.f);

    for (int jb = 0; jb <= qi; jb++) {
        const int s0 = jb * 64;
        __syncthreads();   // prev iter done with Kh/Vh/Sh/St
        // ---- load K (and V) tiles, split hi/lo ----
        {
            const float* kp = g_k + base + (size_t)(s0 + r) * D_ + c0;
#pragma unroll
            for (int u = 0; u < 8; u++) {
                const float4 a = *(const float4*)(kp + u * 4);
                float av[4] = {a.x, a.y, a.z, a.w};
#pragma unroll
                for (int e = 0; e < 4; e++) {
                    const __nv_bfloat16 h = __float2bfloat16(av[e]);
                    Kh[r * LDA + c0 + u * 4 + e] = h;
                    Kl[r * LDA + c0 + u * 4 + e] = __float2bfloat16(av[e] - __bfloat162float(h));
                }
            }
            if (MODE == 1) {
                const float* vp = g_v + base + (size_t)(s0 + r) * D_ + c0;
#pragma unroll
                for (int u = 0; u < 8; u++) {
                    const float4 a = *(const float4*)(vp + u * 4);
                    float av[4] = {a.x, a.y, a.z, a.w};
#pragma unroll
                    for (int e = 0; e < 4; e++) {
                        const __nv_bfloat16 h = __float2bfloat16(av[e]);
                        Vh[r * LDA + c0 + u * 4 + e] = h;
                        Vl[r * LDA + c0 + u * 4 + e] = __float2bfloat16(av[e] - __bfloat162float(h));
                    }
                }
            }
        }
        __syncthreads();

        // ---- phase 1: S = Qeff * K^T ----
        wmma::fragment<wmma::accumulator, 16, 16, 16, float> accS[4];
#pragma unroll
        for (int j = 0; j < 4; j++) wmma::fill_fragment(accS[j], 0.f);
#pragma unroll
        for (int kt = 0; kt < 4; kt++) {
            wmma::fragment<wmma::matrix_a, 16, 16, 16, __nv_bfloat16, wmma::row_major> a_h, a_l;
            wmma::load_matrix_sync(a_h, &Qh[(w * 16) * LDA + kt * 16], LDA);
            wmma::load_matrix_sync(a_l, &Ql[(w * 16) * LDA + kt * 16], LDA);
#pragma unroll
            for (int j = 0; j < 4; j++) {
                wmma::fragment<wmma::matrix_b, 16, 16, 16, __nv_bfloat16, wmma::col_major> b_h, b_l;
                wmma::load_matrix_sync(b_h, &Kh[(j * 16) * LDA + kt * 16], LDA);
                wmma::load_matrix_sync(b_l, &Kl[(j * 16) * LDA + kt * 16], LDA);
                wmma::mma_sync(accS[j], a_h, b_h, accS[j]);
                wmma::mma_sync(accS[j], a_h, b_l, accS[j]);
                wmma::mma_sync(accS[j], a_l, b_h, accS[j]);
            }
        }
        // stage S to smem float
#pragma unroll
        for (int j = 0; j < 4; j++)
            wmma::store_matrix_sync(&St[(w * 16) * LDA + j * 16], accS[j], LDA, wmma::mem_row_major);
        __syncthreads();

        // ---- mask (diag block) + convert S to bf16 hi/lo ----
        {
            const bool diag = (jb == qi);
#pragma unroll
            for (int u = 0; u < 32; u++) {
                const int s = c0 + u;
                float val = St[r * LDA + s];
                if (diag && s > r) val = 0.f;
                const __nv_bfloat16 h = __float2bfloat16(val);
                Sh[r * LDA + s] = h;
                Sl[r * LDA + s] = __float2bfloat16(val - __bfloat162float(h));
            }
        }
        __syncthreads();

        // ---- phase 2: O += S * V ----
#pragma unroll
        for (int kt = 0; kt < 4; kt++) {
            wmma::fragment<wmma::matrix_a, 16, 16, 16, __nv_bfloat16, wmma::row_major> a_h, a_l;
            wmma::load_matrix_sync(a_h, &Sh[(w * 16) * LDA + kt * 16], LDA);
            wmma::load_matrix_sync(a_l, &Sl[(w * 16) * LDA + kt * 16], LDA);
#pragma unroll
            for (int j = 0; j < 4; j++) {
                wmma::fragment<wmma::matrix_b, 16, 16, 16, __nv_bfloat16, wmma::row_major> b_h, b_l;
                wmma::load_matrix_sync(b_h, &Vh[(kt * 16) * LDA + j * 16], LDA);
                wmma::load_matrix_sync(b_l, &Vl[(kt * 16) * LDA + j * 16], LDA);
                wmma::mma_sync(accO[j], a_h, b_h, accO[j]);
                wmma::mma_sync(accO[j], a_h, b_l, accO[j]);
                wmma::mma_sync(accO[j], a_l, b_h, accO[j]);
            }
        }
    }

    // ---- epilogue: store O fragments directly to global ----
    float* Out = (MODE == 0) ? g_o2 : g_ctx;
#pragma unroll
    for (int j = 0; j < 4; j++)
        wmma::store_matrix_sync(&Out[base + (size_t)(t0 + w * 16) * D_ + j * 16],
                                accO[j], D_, wmma::mem_row_major);
}

// ============================================================
// Kernel 4: per-(b,h) normalization (VERBATIM round-1)
// ============================================================
__device__ __forceinline__ double warpReduceSumD(double v) {
#pragma unroll
    for (int o = 16; o > 0; o >>= 1) v += __shfl_down_sync(0xffffffffu, v, o);
    return v;
}

__global__ void __launch_bounds__(512) gn_kernel(const float* __restrict__ gn_w,
                                                 const float* __restrict__ gn_b) {
    const int bh = blockIdx.x;            // 0..31
    const int b_idx = bh / H_, h = bh % H_;
    const float* src = g_ctx + (size_t)bh * S_ * D_;
    const int N = S_ * D_;                // 131072

    double sum = 0.0, sq = 0.0;
    for (int i = threadIdx.x; i < N; i += 512) {
        const float v = src[i];
        sum += v;
        sq += (double)v * (double)v;
    }
    __shared__ double ssum[16], ssq[16];
    const int lane = threadIdx.x & 31, wid = threadIdx.x >> 5;
    sum = warpReduceSumD(sum);
    sq = warpReduceSumD(sq);
    if (lane == 0) { ssum[wid] = sum; ssq[wid] = sq; }
    __syncthreads();
    __shared__ float s_mean, s_rstd;
    if (threadIdx.x == 0) {
        double ts = 0.0, tq = 0.0;
        for (int i = 0; i < 16; i++) { ts += ssum[i]; tq += ssq[i]; }
        const double mean = ts / (double)N;
        const double var = tq / (double)N - mean * mean;
        s_mean = (float)mean;
        s_rstd = (float)rsqrt(var + 1e-5);
    }
    __syncthreads();
    const float mean = s_mean, rstd = s_rstd;
    for (int i = threadIdx.x; i < N; i += 512) {
        const int t = i >> 6, d = i & 63;
        const int col = h * D_ + d;
        g_normed[((size_t)b_idx * S_ + t) * DM_ + col] =
            (src[i] - mean) * rstd * gn_w[col] + gn_b[col];
    }
}

// ============================================================
extern "C" void kernel_launch(void* const* d_in, const int* in_sizes, int n_in,
                              void* d_out, int out_size) {
    const float* x       = (const float*)d_in[0];
    const float* Wproj_w = (const float*)d_in[1];
    const float* Wproj_b = (const float*)d_in[2];
    const float* out_w   = (const float*)d_in[3];
    const float* out_b   = (const float*)d_in[4];
    const float* gn_w    = (const float*)d_in[5];
    const float* gn_b    = (const float*)d_in[6];
    float* out = (float*)d_out;

    // attention smem: MODE0 = 6 bf16 tiles + St; MODE1 = 8 bf16 tiles + St
    const int smem0 = 6 * TSZ * 2 + 64 * LDA * 4;   // 73728
    const int smem1 = 8 * TSZ * 2 + 64 * LDA * 4;   // 92160
    cudaFuncSetAttribute(attn_wmma_kernel<0>, cudaFuncAttributeMaxDynamicSharedMemorySize, smem0);
    cudaFuncSetAttribute(attn_wmma_kernel<1>, cudaFuncAttributeMaxDynamicSharedMemorySize, smem1);

    // 1) QKV projection + scatter — WMMA bf16 hi/lo
    qkv_wmma_kernel<<<dim3(24, 32), 256>>>(x, Wproj_w, Wproj_b);
    // 2) pass A: o2 = causal(q,k,k) — WMMA attention
    attn_wmma_kernel<0><<<dim3(32, BH_), 128, smem0>>>();
    // 3) pass B: ctx = causal(2q-o2, k, v) — WMMA attention
    attn_wmma_kernel<1><<<dim3(32, BH_), 128, smem1>>>();
    // 4) per-(b,h) norm + scatter
    gn_kernel<<<BH_, 512>>>(gn_w, gn_b);
    // 5) output projection — WMMA bf16 hi/lo
    out_wmma_kernel<<<dim3(8, 32), 256>>>(out_w, out_b, out);
}

// round 16
// speedup vs baseline: 1.6012x; 1.1291x over previous

#include <cuda_runtime.h>
#include <cuda_bf16.h>
#include <mma.h>
#include <math.h>
#include <stdint.h>

using namespace nvcuda;

#define B_  2
#define S_  2048
#define H_  16
#define D_  64
#define DM_ 1024
#define BH_ (B_ * H_)
#define QKV_ELEMS ((size_t)BH_ * S_ * D_)

// -------- scratch (device globals: allocation-free) --------
__device__ float g_q[QKV_ELEMS];          // fp32 q (for Qeff in pass B)
__device__ float g_o2[QKV_ELEMS];         // fp32 o2
__device__ float g_ctx[QKV_ELEMS];        // fp32 ctx
__device__ __nv_bfloat16 g_qh[QKV_ELEMS], g_ql[QKV_ELEMS];
__device__ __nv_bfloat16 g_kh[QKV_ELEMS], g_kl[QKV_ELEMS];
__device__ __nv_bfloat16 g_vh[QKV_ELEMS], g_vl[QKV_ELEMS];
__device__ __nv_bfloat16 g_xh[(size_t)B_ * S_ * DM_], g_xl[(size_t)B_ * S_ * DM_];
__device__ __nv_bfloat16 g_wh[(size_t)3 * DM_ * DM_], g_wl[(size_t)3 * DM_ * DM_];
__device__ __nv_bfloat16 g_owh[(size_t)DM_ * DM_], g_owl[(size_t)DM_ * DM_];
__device__ __nv_bfloat16 g_nh[(size_t)B_ * S_ * DM_], g_nl[(size_t)B_ * S_ * DM_];

// ---------------- bf16 split helpers ----------------
__device__ __forceinline__ void split1(float x, __nv_bfloat16& h, __nv_bfloat16& l) {
    h = __float2bfloat16(x);
    l = __float2bfloat16(x - __bfloat162float(h));
}

// ============================================================
// Kernel 0: elementwise fp32 -> bf16 hi/lo split (grid-stride, x4)
// ============================================================
__global__ void __launch_bounds__(256) split_kernel(
    const float* __restrict__ src, __nv_bfloat16* __restrict__ h,
    __nv_bfloat16* __restrict__ l, int n4) {
    for (int i = blockIdx.x * 256 + threadIdx.x; i < n4; i += gridDim.x * 256) {
        const float4 a = ((const float4*)src)[i];
        __nv_bfloat16 h0, l0, h1, l1, h2, l2, h3, l3;
        split1(a.x, h0, l0); split1(a.y, h1, l1);
        split1(a.z, h2, l2); split1(a.w, h3, l3);
        ushort4 hv, lv;
        hv.x = __bfloat16_as_ushort(h0); hv.y = __bfloat16_as_ushort(h1);
        hv.z = __bfloat16_as_ushort(h2); hv.w = __bfloat16_as_ushort(h3);
        lv.x = __bfloat16_as_ushort(l0); lv.y = __bfloat16_as_ushort(l1);
        lv.z = __bfloat16_as_ushort(l2); lv.w = __bfloat16_as_ushort(l3);
        ((ushort4*)h)[i] = hv;
        ((ushort4*)l)[i] = lv;
    }
}

#define LDT 24   // bf16 leading dim for GEMM tiles (48B)

// ============================================================
// Kernel 1: QKV projection via WMMA, pre-split bf16 operands.
// Epilogue: q -> fp32 + bf16 hi/lo; k,v -> bf16 hi/lo.
// ============================================================
__global__ void __launch_bounds__(256) qkv_wmma_kernel(const float* __restrict__ bias) {
    __shared__ __nv_bfloat16 Ah[128 * LDT], Al[128 * LDT];
    __shared__ __nv_bfloat16 Bh[128 * LDT], Bl[128 * LDT];
    __shared__ float stage[8][256];

    const int bm = blockIdx.y * 128, bn = blockIdx.x * 128;
    const int tid = threadIdx.x;
    const int warp = tid >> 5, lane = tid & 31;
    const int wm = warp >> 2, wn = warp & 3;     // 2x4 warp grid
    const int lrow = tid >> 1;                   // 0..127
    const int lk = (tid & 1) * 8;                // 0 or 8

    wmma::fragment<wmma::accumulator, 16, 16, 16, float> c[4][2];
#pragma unroll
    for (int i = 0; i < 4; i++)
#pragma unroll
        for (int j = 0; j < 2; j++) wmma::fill_fragment(c[i][j], 0.f);

    for (int k0 = 0; k0 < 1024; k0 += 16) {
        const uint4 a_h = *(const uint4*)&g_xh[(size_t)(bm + lrow) * 1024 + k0 + lk];
        const uint4 a_l = *(const uint4*)&g_xl[(size_t)(bm + lrow) * 1024 + k0 + lk];
        const uint4 b_h = *(const uint4*)&g_wh[(size_t)(bn + lrow) * 1024 + k0 + lk];
        const uint4 b_l = *(const uint4*)&g_wl[(size_t)(bn + lrow) * 1024 + k0 + lk];
        __syncthreads();
        *(uint4*)&Ah[lrow * LDT + lk] = a_h;
        *(uint4*)&Al[lrow * LDT + lk] = a_l;
        *(uint4*)&Bh[lrow * LDT + lk] = b_h;
        *(uint4*)&Bl[lrow * LDT + lk] = b_l;
        __syncthreads();

        wmma::fragment<wmma::matrix_a, 16, 16, 16, __nv_bfloat16, wmma::row_major> f_ah[4], f_al[4];
#pragma unroll
        for (int i = 0; i < 4; i++) {
            wmma::load_matrix_sync(f_ah[i], &Ah[(wm * 64 + i * 16) * LDT], LDT);
            wmma::load_matrix_sync(f_al[i], &Al[(wm * 64 + i * 16) * LDT], LDT);
        }
#pragma unroll
        for (int j = 0; j < 2; j++) {
            wmma::fragment<wmma::matrix_b, 16, 16, 16, __nv_bfloat16, wmma::col_major> f_bh, f_bl;
            wmma::load_matrix_sync(f_bh, &Bh[(wn * 32 + j * 16) * LDT], LDT);
            wmma::load_matrix_sync(f_bl, &Bl[(wn * 32 + j * 16) * LDT], LDT);
#pragma unroll
            for (int i = 0; i < 4; i++) {
                wmma::mma_sync(c[i][j], f_ah[i], f_bh, c[i][j]);
                wmma::mma_sync(c[i][j], f_ah[i], f_bl, c[i][j]);
                wmma::mma_sync(c[i][j], f_al[i], f_bh, c[i][j]);
            }
        }
    }

    const int r = lane >> 1;            // 0..15
    const int c0 = (lane & 1) * 8;      // 0 or 8
#pragma unroll
    for (int i = 0; i < 4; i++) {
#pragma unroll
        for (int j = 0; j < 2; j++) {
            wmma::store_matrix_sync(stage[warp], c[i][j], 16, wmma::mem_row_major);
            __syncwarp();
            const int m = bm + wm * 64 + i * 16 + r;
            const int b_idx = m >> 11, s_idx = m & 2047;
#pragma unroll
            for (int u = 0; u < 8; u++) {
                const int n = bn + wn * 32 + j * 16 + c0 + u;
                const float val = stage[warp][r * 16 + c0 + u] + bias[n];
                const int which = n >> 10;
                const int wi = n & 1023;
                const int h = wi >> 6, d = wi & 63;
                const size_t idx = (((size_t)b_idx * H_ + h) * S_ + s_idx) * D_ + d;
                __nv_bfloat16 hv, lv;
                split1(val, hv, lv);
                if (which == 0) {
                    g_q[idx] = val; g_qh[idx] = hv; g_ql[idx] = lv;
                } else if (which == 1) {
                    g_kh[idx] = hv; g_kl[idx] = lv;
                } else {
                    g_vh[idx] = hv; g_vl[idx] = lv;
                }
            }
            __syncwarp();
        }
    }
}

// ============================================================
// Kernel 5: output projection via WMMA, pre-split bf16 operands.
// ============================================================
__global__ void __launch_bounds__(256) out_wmma_kernel(
    const float* __restrict__ bias, float* __restrict__ out) {
    __shared__ __nv_bfloat16 Ah[128 * LDT], Al[128 * LDT];
    __shared__ __nv_bfloat16 Bh[128 * LDT], Bl[128 * LDT];
    __shared__ float stage[8][256];

    const int bm = blockIdx.y * 128, bn = blockIdx.x * 128;
    const int tid = threadIdx.x;
    const int warp = tid >> 5, lane = tid & 31;
    const int wm = warp >> 2, wn = warp & 3;
    const int lrow = tid >> 1;
    const int lk = (tid & 1) * 8;

    wmma::fragment<wmma::accumulator, 16, 16, 16, float> c[4][2];
#pragma unroll
    for (int i = 0; i < 4; i++)
#pragma unroll
        for (int j = 0; j < 2; j++) wmma::fill_fragment(c[i][j], 0.f);

    for (int k0 = 0; k0 < 1024; k0 += 16) {
        const uint4 a_h = *(const uint4*)&g_nh[(size_t)(bm + lrow) * 1024 + k0 + lk];
        const uint4 a_l = *(const uint4*)&g_nl[(size_t)(bm + lrow) * 1024 + k0 + lk];
        const uint4 b_h = *(const uint4*)&g_owh[(size_t)(bn + lrow) * 1024 + k0 + lk];
        const uint4 b_l = *(const uint4*)&g_owl[(size_t)(bn + lrow) * 1024 + k0 + lk];
        __syncthreads();
        *(uint4*)&Ah[lrow * LDT + lk] = a_h;
        *(uint4*)&Al[lrow * LDT + lk] = a_l;
        *(uint4*)&Bh[lrow * LDT + lk] = b_h;
        *(uint4*)&Bl[lrow * LDT + lk] = b_l;
        __syncthreads();

        wmma::fragment<wmma::matrix_a, 16, 16, 16, __nv_bfloat16, wmma::row_major> f_ah[4], f_al[4];
#pragma unroll
        for (int i = 0; i < 4; i++) {
            wmma::load_matrix_sync(f_ah[i], &Ah[(wm * 64 + i * 16) * LDT], LDT);
            wmma::load_matrix_sync(f_al[i], &Al[(wm * 64 + i * 16) * LDT], LDT);
        }
#pragma unroll
        for (int j = 0; j < 2; j++) {
            wmma::fragment<wmma::matrix_b, 16, 16, 16, __nv_bfloat16, wmma::col_major> f_bh, f_bl;
            wmma::load_matrix_sync(f_bh, &Bh[(wn * 32 + j * 16) * LDT], LDT);
            wmma::load_matrix_sync(f_bl, &Bl[(wn * 32 + j * 16) * LDT], LDT);
#pragma unroll
            for (int i = 0; i < 4; i++) {
                wmma::mma_sync(c[i][j], f_ah[i], f_bh, c[i][j]);
                wmma::mma_sync(c[i][j], f_ah[i], f_bl, c[i][j]);
                wmma::mma_sync(c[i][j], f_al[i], f_bh, c[i][j]);
            }
        }
    }

    const int r = lane >> 1;
    const int c0 = (lane & 1) * 8;
#pragma unroll
    for (int i = 0; i < 4; i++) {
#pragma unroll
        for (int j = 0; j < 2; j++) {
            wmma::store_matrix_sync(stage[warp], c[i][j], 16, wmma::mem_row_major);
            __syncwarp();
            const int m = bm + wm * 64 + i * 16 + r;
#pragma unroll
            for (int u = 0; u < 2; u++) {
                const int n = bn + wn * 32 + j * 16 + c0 + u * 4;
                const float4 bb = *(const float4*)&bias[n];
                float4 v;
                v.x = stage[warp][r * 16 + c0 + u * 4 + 0] + bb.x;
                v.y = stage[warp][r * 16 + c0 + u * 4 + 1] + bb.y;
                v.z = stage[warp][r * 16 + c0 + u * 4 + 2] + bb.z;
                v.w = stage[warp][r * 16 + c0 + u * 4 + 3] + bb.w;
                *(float4*)&out[(size_t)m * DM_ + n] = v;
            }
            __syncwarp();
        }
    }
}

// ============================================================
// Kernel 2/3: causal no-softmax attention via WMMA bf16 hi/lo.
// MODE 0: Qeff = q (pre-split), V = k (reuses K tiles), Out = o2
// MODE 1: Qeff = 2q - o2 (split in-kernel), V = v,      Out = ctx
// K/V tiles are straight bf16 copies — no conversion in hot loop.
// ============================================================
#define LDA 72
#define TSZ (64 * LDA)

template <int MODE>
__global__ void __launch_bounds__(128) attn_wmma_kernel() {
    extern __shared__ __nv_bfloat16 smb[];
    __nv_bfloat16* Qh = smb;
    __nv_bfloat16* Ql = smb + TSZ;
    __nv_bfloat16* Kh = smb + 2 * TSZ;
    __nv_bfloat16* Kl = smb + 3 * TSZ;
    __nv_bfloat16* Sh = smb + 4 * TSZ;
    __nv_bfloat16* Sl = smb + 5 * TSZ;
    __nv_bfloat16* Vh = (MODE == 0) ? Kh : smb + 6 * TSZ;
    __nv_bfloat16* Vl = (MODE == 0) ? Kl : smb + 7 * TSZ;
    float* St = (float*)(smb + ((MODE == 0) ? 6 : 8) * TSZ);   // [64][72] float

    const int bh = blockIdx.y;
    const int qi = gridDim.x - 1 - blockIdx.x;   // largest blocks first
    const size_t base = (size_t)bh * S_ * D_;
    const int t0 = qi * 64;
    const int tid = threadIdx.x;
    const int w = tid >> 5;
    const int r = tid >> 1;              // 0..63
    const int c0 = (tid & 1) * 32;       // 0 or 32

    // ---- load Q (Qeff), hi/lo ----
    if (MODE == 0) {
        const size_t off = base + (size_t)(t0 + r) * D_ + c0;
#pragma unroll
        for (int u = 0; u < 4; u++) {
            *(uint4*)&Qh[r * LDA + c0 + u * 8] = *(const uint4*)&g_qh[off + u * 8];
            *(uint4*)&Ql[r * LDA + c0 + u * 8] = *(const uint4*)&g_ql[off + u * 8];
        }
    } else {
        const float* qp = g_q + base + (size_t)(t0 + r) * D_ + c0;
        const float* op = g_o2 + base + (size_t)(t0 + r) * D_ + c0;
#pragma unroll
        for (int u = 0; u < 8; u++) {
            float4 a = *(const float4*)(qp + u * 4);
            const float4 o = *(const float4*)(op + u * 4);
            a.x = 2.f * a.x - o.x; a.y = 2.f * a.y - o.y;
            a.z = 2.f * a.z - o.z; a.w = 2.f * a.w - o.w;
            float av[4] = {a.x, a.y, a.z, a.w};
#pragma unroll
            for (int e = 0; e < 4; e++) {
                __nv_bfloat16 h, l;
                split1(av[e], h, l);
                Qh[r * LDA + c0 + u * 4 + e] = h;
                Ql[r * LDA + c0 + u * 4 + e] = l;
            }
        }
    }

    wmma::fragment<wmma::accumulator, 16, 16, 16, float> accO[4];
#pragma unroll
    for (int j = 0; j < 4; j++) wmma::fill_fragment(accO[j], 0.f);

    for (int jb = 0; jb <= qi; jb++) {
        const int s0 = jb * 64;
        __syncthreads();   // prev iter done with Kh/Vh/Sh/St
        // ---- copy K (and V) bf16 tiles ----
        {
            const size_t off = base + (size_t)(s0 + r) * D_ + c0;
#pragma unroll
            for (int u = 0; u < 4; u++) {
                *(uint4*)&Kh[r * LDA + c0 + u * 8] = *(const uint4*)&g_kh[off + u * 8];
                *(uint4*)&Kl[r * LDA + c0 + u * 8] = *(const uint4*)&g_kl[off + u * 8];
            }
            if (MODE == 1) {
#pragma unroll
                for (int u = 0; u < 4; u++) {
                    *(uint4*)&Vh[r * LDA + c0 + u * 8] = *(const uint4*)&g_vh[off + u * 8];
                    *(uint4*)&Vl[r * LDA + c0 + u * 8] = *(const uint4*)&g_vl[off + u * 8];
                }
            }
        }
        __syncthreads();

        // ---- phase 1: S = Qeff * K^T ----
        wmma::fragment<wmma::accumulator, 16, 16, 16, float> accS[4];
#pragma unroll
        for (int j = 0; j < 4; j++) wmma::fill_fragment(accS[j], 0.f);
#pragma unroll
        for (int kt = 0; kt < 4; kt++) {
            wmma::fragment<wmma::matrix_a, 16, 16, 16, __nv_bfloat16, wmma::row_major> a_h, a_l;
            wmma::load_matrix_sync(a_h, &Qh[(w * 16) * LDA + kt * 16], LDA);
            wmma::load_matrix_sync(a_l, &Ql[(w * 16) * LDA + kt * 16], LDA);
#pragma unroll
            for (int j = 0; j < 4; j++) {
                wmma::fragment<wmma::matrix_b, 16, 16, 16, __nv_bfloat16, wmma::col_major> b_h, b_l;
                wmma::load_matrix_sync(b_h, &Kh[(j * 16) * LDA + kt * 16], LDA);
                wmma::load_matrix_sync(b_l, &Kl[(j * 16) * LDA + kt * 16], LDA);
                wmma::mma_sync(accS[j], a_h, b_h, accS[j]);
                wmma::mma_sync(accS[j], a_h, b_l, accS[j]);
                wmma::mma_sync(accS[j], a_l, b_h, accS[j]);
            }
        }
#pragma unroll
        for (int j = 0; j < 4; j++)
            wmma::store_matrix_sync(&St[(w * 16) * LDA + j * 16], accS[j], LDA, wmma::mem_row_major);
        __syncthreads();

        // ---- mask (diag block) + convert S to bf16 hi/lo ----
        {
            const bool diag = (jb == qi);
#pragma unroll
            for (int u = 0; u < 32; u++) {
                const int s = c0 + u;
                float val = St[r * LDA + s];
                if (diag && s > r) val = 0.f;
                __nv_bfloat16 h, l;
                split1(val, h, l);
                Sh[r * LDA + s] = h;
                Sl[r * LDA + s] = l;
            }
        }
        __syncthreads();

        // ---- phase 2: O += S * V ----
#pragma unroll
        for (int kt = 0; kt < 4; kt++) {
            wmma::fragment<wmma::matrix_a, 16, 16, 16, __nv_bfloat16, wmma::row_major> a_h, a_l;
            wmma::load_matrix_sync(a_h, &Sh[(w * 16) * LDA + kt * 16], LDA);
            wmma::load_matrix_sync(a_l, &Sl[(w * 16) * LDA + kt * 16], LDA);
#pragma unroll
            for (int j = 0; j < 4; j++) {
                wmma::fragment<wmma::matrix_b, 16, 16, 16, __nv_bfloat16, wmma::row_major> b_h, b_l;
                wmma::load_matrix_sync(b_h, &Vh[(kt * 16) * LDA + j * 16], LDA);
                wmma::load_matrix_sync(b_l, &Vl[(kt * 16) * LDA + j * 16], LDA);
                wmma::mma_sync(accO[j], a_h, b_h, accO[j]);
                wmma::mma_sync(accO[j], a_h, b_l, accO[j]);
                wmma::mma_sync(accO[j], a_l, b_h, accO[j]);
            }
        }
    }

    // ---- epilogue ----
    float* Out = (MODE == 0) ? g_o2 : g_ctx;
#pragma unroll
    for (int j = 0; j < 4; j++)
        wmma::store_matrix_sync(&Out[base + (size_t)(t0 + w * 16) * D_ + j * 16],
                                accO[j], D_, wmma::mem_row_major);
}

// ============================================================
// Kernel 4: per-(b,h) normalization; writes normed as bf16 hi/lo.
// ============================================================
__device__ __forceinline__ double warpReduceSumD(double v) {
#pragma unroll
    for (int o = 16; o > 0; o >>= 1) v += __shfl_down_sync(0xffffffffu, v, o);
    return v;
}

__global__ void __launch_bounds__(512) gn_kernel(const float* __restrict__ gn_w,
                                                 const float* __restrict__ gn_b) {
    const int bh = blockIdx.x;            // 0..31
    const int b_idx = bh / H_, h = bh % H_;
    const float* src = g_ctx + (size_t)bh * S_ * D_;
    const int N = S_ * D_;                // 131072

    double sum = 0.0, sq = 0.0;
    for (int i = threadIdx.x; i < N; i += 512) {
        const float v = src[i];
        sum += v;
        sq += (double)v * (double)v;
    }
    __shared__ double ssum[16], ssq[16];
    const int lane = threadIdx.x & 31, wid = threadIdx.x >> 5;
    sum = warpReduceSumD(sum);
    sq = warpReduceSumD(sq);
    if (lane == 0) { ssum[wid] = sum; ssq[wid] = sq; }
    __syncthreads();
    __shared__ float s_mean, s_rstd;
    if (threadIdx.x == 0) {
        double ts = 0.0, tq = 0.0;
        for (int i = 0; i < 16; i++) { ts += ssum[i]; tq += ssq[i]; }
        const double mean = ts / (double)N;
        const double var = tq / (double)N - mean * mean;
        s_mean = (float)mean;
        s_rstd = (float)rsqrt(var + 1e-5);
    }
    __syncthreads();
    const float mean = s_mean, rstd = s_rstd;
    for (int i = threadIdx.x; i < N; i += 512) {
        const int t = i >> 6, d = i & 63;
        const int col = h * D_ + d;
        const float val = (src[i] - mean) * rstd * gn_w[col] + gn_b[col];
        const size_t idx = ((size_t)b_idx * S_ + t) * DM_ + col;
        __nv_bfloat16 hv, lv;
        split1(val, hv, lv);
        g_nh[idx] = hv;
        g_nl[idx] = lv;
    }
}

// ============================================================
extern "C" void kernel_launch(void* const* d_in, const int* in_sizes, int n_in,
                              void* d_out, int out_size) {
    const float* x       = (const float*)d_in[0];
    const float* Wproj_w = (const float*)d_in[1];
    const float* Wproj_b = (const float*)d_in[2];
    const float* out_w   = (const float*)d_in[3];
    const float* out_b   = (const float*)d_in[4];
    const float* gn_w    = (const float*)d_in[5];
    const float* gn_b    = (const float*)d_in[6];
    float* out = (float*)d_out;

    const int smem0 = 6 * TSZ * 2 + 64 * LDA * 4;   // 73728
    const int smem1 = 8 * TSZ * 2 + 64 * LDA * 4;   // 92160
    cudaFuncSetAttribute(attn_wmma_kernel<0>, cudaFuncAttributeMaxDynamicSharedMemorySize, smem0);
    cudaFuncSetAttribute(attn_wmma_kernel<1>, cudaFuncAttributeMaxDynamicSharedMemorySize, smem1);

    // device-global addresses for split targets
    __nv_bfloat16 *xh, *xl, *wh, *wl, *owh, *owl;
    cudaGetSymbolAddress((void**)&xh, g_xh);  cudaGetSymbolAddress((void**)&xl, g_xl);
    cudaGetSymbolAddress((void**)&wh, g_wh);  cudaGetSymbolAddress((void**)&wl, g_wl);
    cudaGetSymbolAddress((void**)&owh, g_owh); cudaGetSymbolAddress((void**)&owl, g_owl);

    // 0) pre-split inputs to bf16 hi/lo
    split_kernel<<<2048, 256>>>(x, xh, xl, (B_ * S_ * DM_) / 4);
    split_kernel<<<2048, 256>>>(Wproj_w, wh, wl, (3 * DM_ * DM_) / 4);
    split_kernel<<<1024, 256>>>(out_w, owh, owl, (DM_ * DM_) / 4);

    // 1) QKV projection + scatter (bf16 operands)
    qkv_wmma_kernel<<<dim3(24, 32), 256>>>(Wproj_b);
    // 2) pass A: o2 = causal(q,k,k)
    attn_wmma_kernel<0><<<dim3(32, BH_), 128, smem0>>>();
    // 3) pass B: ctx = causal(2q-o2, k, v)
    attn_wmma_kernel<1><<<dim3(32, BH_), 128, smem1>>>();
    // 4) per-(b,h) norm + scatter (writes bf16 hi/lo)
    gn_kernel<<<BH_, 512>>>(gn_w, gn_b);
    // 5) output projection (bf16 operands)
    out_wmma_kernel<<<dim3(8, 32), 256>>>(out_b, out);
}